// round 9
// baseline (speedup 1.0000x reference)
#include <cuda_runtime.h>
#include <cuda_fp16.h>
#include <cuda_bf16.h>
#include <cstdint>

// ---------------------------------------------------------------------------
// MultiScaleDETR deformable attention.
// B=4, Q=8400, D=256, nH=8, hd=32, L=3 (80x80,40x40,20x20), P=4.
// tf32 GEMMs for value/output; fused 3xBF16 split GEMM (N=288) for
// offset+attn logits on pre-split bf16 query; branch-free fp16 sampler.
// ---------------------------------------------------------------------------

#define B_    4
#define Q_    8400
#define D_    256
#define NH_   8
#define HD_   32
#define NL_   3
#define NP_   4
#define S_    8400
#define MQ_   (B_ * Q_)      // 33600

__device__ __half         g_Vh [B_ * S_ * D_];  // value projection, fp16
__device__ float          g_OFF[MQ_ * 192];     // tanh(offset_logit)*0.5
__device__ float          g_ATT[MQ_ * 96];      // attn logits -> softmaxed
__device__ float          g_MID[MQ_ * D_];      // attention output pre-W_out
__device__ __nv_bfloat16  g_QH [MQ_ * D_];      // query bf16 hi
__device__ __nv_bfloat16  g_QL [MQ_ * D_];      // query bf16 lo (residual)

// ---------------------------------------------------------------------------
// mma helpers
// ---------------------------------------------------------------------------
__device__ __forceinline__ uint32_t f2tf32(float f) {
    uint32_t u;
    asm("cvt.rna.tf32.f32 %0, %1;" : "=r"(u) : "f"(f));
    return u;
}

__device__ __forceinline__ void mma_tf32(float* d, const uint32_t* a, const uint32_t* b) {
    asm volatile(
        "mma.sync.aligned.m16n8k8.row.col.f32.tf32.tf32.f32 "
        "{%0,%1,%2,%3}, {%4,%5,%6,%7}, {%8,%9}, {%0,%1,%2,%3};\n"
        : "+f"(d[0]), "+f"(d[1]), "+f"(d[2]), "+f"(d[3])
        : "r"(a[0]), "r"(a[1]), "r"(a[2]), "r"(a[3]), "r"(b[0]), "r"(b[1]));
}

__device__ __forceinline__ void mma_bf16(float* d, const uint32_t* a, const uint32_t* b) {
    asm volatile(
        "mma.sync.aligned.m16n8k16.row.col.f32.bf16.bf16.f32 "
        "{%0,%1,%2,%3}, {%4,%5,%6,%7}, {%8,%9}, {%0,%1,%2,%3};\n"
        : "+f"(d[0]), "+f"(d[1]), "+f"(d[2]), "+f"(d[3])
        : "r"(a[0]), "r"(a[1]), "r"(a[2]), "r"(a[3]), "r"(b[0]), "r"(b[1]));
}

__device__ __forceinline__ uint32_t pack_bf16(__nv_bfloat16 a, __nv_bfloat16 b) {
    __nv_bfloat162 h; h.x = a; h.y = b;
    return *reinterpret_cast<uint32_t*>(&h);
}

// ---------------------------------------------------------------------------
// Pre-split query to bf16 hi/lo (one pass).
// ---------------------------------------------------------------------------
__global__ void split_query(const float* __restrict__ q) {
    int i = blockIdx.x * blockDim.x + threadIdx.x;   // float4 index
    if (i >= MQ_ * D_ / 4) return;
    float4 v = *reinterpret_cast<const float4*>(q + (size_t)i * 4);
    __nv_bfloat16 h0 = __float2bfloat16_rn(v.x);
    __nv_bfloat16 h1 = __float2bfloat16_rn(v.y);
    __nv_bfloat16 h2 = __float2bfloat16_rn(v.z);
    __nv_bfloat16 h3 = __float2bfloat16_rn(v.w);
    __nv_bfloat16 l0 = __float2bfloat16_rn(v.x - __bfloat162float(h0));
    __nv_bfloat16 l1 = __float2bfloat16_rn(v.y - __bfloat162float(h1));
    __nv_bfloat16 l2 = __float2bfloat16_rn(v.z - __bfloat162float(h2));
    __nv_bfloat16 l3 = __float2bfloat16_rn(v.w - __bfloat162float(h3));
    uint2 uh, ul;
    uh.x = pack_bf16(h0, h1); uh.y = pack_bf16(h2, h3);
    ul.x = pack_bf16(l0, l1); ul.y = pack_bf16(l2, l3);
    *reinterpret_cast<uint2*>(&g_QH[(size_t)i * 4]) = uh;
    *reinterpret_cast<uint2*>(&g_QL[(size_t)i * 4]) = ul;
}

// ---------------------------------------------------------------------------
// Fused offset+attn logits: 3xBF16 split GEMM over N=288.
// Columns [0,192): W_off, tanh(x+b)*0.5 -> g_OFF.
// Columns [192,288): W_att, x+b -> g_ATT.
// BN=64 so no block mixes the two weight sources (n0<192 vs n0>=192).
// A is pre-split bf16 (g_QH/g_QL) -> stage is a pure copy.
// ---------------------------------------------------------------------------
__global__ void gemm_off_att_3xbf16(const float* __restrict__ Woff, const float* __restrict__ boff,
                                    const float* __restrict__ Watt, const float* __restrict__ batt) {
    __shared__ __align__(16) uint32_t AsH[128][12];  // packed bf16 pairs along k
    __shared__ __align__(16) uint32_t AsL[128][12];
    __shared__ __align__(16) uint32_t BsH[8][72];
    __shared__ __align__(16) uint32_t BsL[8][72];
    const int tid  = threadIdx.x;
    const int lane = tid & 31;
    const int warp = tid >> 5;
    const int g  = lane >> 2, t4 = lane & 3;
    const int wm = warp >> 1, wn = warp & 1;
    const int m0 = blockIdx.x * 128, n0 = blockIdx.y * 64;
    const int M = MQ_, K = D_;
    const bool is_off = (n0 < 192);
    const float* W  = is_off ? Woff : Watt;
    const float* bb = is_off ? boff : batt;
    const int Nw    = is_off ? 192 : 96;
    const int nbase = is_off ? n0 : n0 - 192;    // column base within W

    float acc[2][4][4] = {};

    for (int k0 = 0; k0 < K; k0 += 16) {
        // stage A: copy pre-split bf16 (128 rows x 16 k = 2 uint4 per row)
        {
            int m  = tid >> 1;             // 0..127
            int q4 = tid & 1;              // which uint4 (8 bf16)
            int gm = m0 + m;
            uint4 uh = make_uint4(0, 0, 0, 0), ul = make_uint4(0, 0, 0, 0);
            if (gm < M) {
                size_t off = (size_t)gm * K + k0 + q4 * 8;
                uh = *reinterpret_cast<const uint4*>(&g_QH[off]);
                ul = *reinterpret_cast<const uint4*>(&g_QL[off]);
            }
            *reinterpret_cast<uint4*>(&AsH[m][q4 * 4]) = uh;
            *reinterpret_cast<uint4*>(&AsL[m][q4 * 4]) = ul;
        }
        // stage B: split W on the fly (weights tiny, reconverted per tile)
        {
            int n  = tid & 63;
            int k2 = tid >> 6;             // 0..3
            int c  = nbase + n;
            bool ok = (c < Nw);
#pragma unroll
            for (int q = 0; q < 2; ++q) {
                int kk = k2 + q * 4;
                float v0 = ok ? W[(size_t)(k0 + 2 * kk)     * Nw + c] : 0.f;
                float v1 = ok ? W[(size_t)(k0 + 2 * kk + 1) * Nw + c] : 0.f;
                __nv_bfloat16 h0 = __float2bfloat16_rn(v0);
                __nv_bfloat16 h1 = __float2bfloat16_rn(v1);
                __nv_bfloat16 l0 = __float2bfloat16_rn(v0 - __bfloat162float(h0));
                __nv_bfloat16 l1 = __float2bfloat16_rn(v1 - __bfloat162float(h1));
                BsH[kk][n] = pack_bf16(h0, h1);
                BsL[kk][n] = pack_bf16(l0, l1);
            }
        }
        __syncthreads();

        uint32_t afH[2][4], afL[2][4], bfH[4][2], bfL[4][2];
#pragma unroll
        for (int mt = 0; mt < 2; ++mt) {
            int rb = wm * 32 + mt * 16;
            afH[mt][0] = AsH[rb + g    ][t4    ];
            afH[mt][1] = AsH[rb + g + 8][t4    ];
            afH[mt][2] = AsH[rb + g    ][t4 + 4];
            afH[mt][3] = AsH[rb + g + 8][t4 + 4];
            afL[mt][0] = AsL[rb + g    ][t4    ];
            afL[mt][1] = AsL[rb + g + 8][t4    ];
            afL[mt][2] = AsL[rb + g    ][t4 + 4];
            afL[mt][3] = AsL[rb + g + 8][t4 + 4];
        }
#pragma unroll
        for (int nt = 0; nt < 4; ++nt) {
            int cb = wn * 32 + nt * 8;
            bfH[nt][0] = BsH[t4    ][cb + g];
            bfH[nt][1] = BsH[t4 + 4][cb + g];
            bfL[nt][0] = BsL[t4    ][cb + g];
            bfL[nt][1] = BsL[t4 + 4][cb + g];
        }
#pragma unroll
        for (int mt = 0; mt < 2; ++mt)
#pragma unroll
            for (int nt = 0; nt < 4; ++nt)
                mma_bf16(acc[mt][nt], afH[mt], bfL[nt]);
#pragma unroll
        for (int mt = 0; mt < 2; ++mt)
#pragma unroll
            for (int nt = 0; nt < 4; ++nt)
                mma_bf16(acc[mt][nt], afL[mt], bfH[nt]);
#pragma unroll
        for (int mt = 0; mt < 2; ++mt)
#pragma unroll
            for (int nt = 0; nt < 4; ++nt)
                mma_bf16(acc[mt][nt], afH[mt], bfH[nt]);
        __syncthreads();
    }

#pragma unroll
    for (int mt = 0; mt < 2; ++mt)
#pragma unroll
        for (int nt = 0; nt < 4; ++nt) {
            int r = m0 + wm * 32 + mt * 16 + g;
            int c = nbase + wn * 32 + nt * 8 + t4 * 2;
            if (c >= Nw) continue;
            float b0 = bb[c], b1 = bb[c + 1];
            float* dst = is_off ? g_OFF : g_ATT;
            if (is_off) {
                if (r < M) {
                    dst[(size_t)r * Nw + c]     = tanhf(acc[mt][nt][0] + b0) * 0.5f;
                    dst[(size_t)r * Nw + c + 1] = tanhf(acc[mt][nt][1] + b1) * 0.5f;
                }
                if (r + 8 < M) {
                    dst[(size_t)(r + 8) * Nw + c]     = tanhf(acc[mt][nt][2] + b0) * 0.5f;
                    dst[(size_t)(r + 8) * Nw + c + 1] = tanhf(acc[mt][nt][3] + b1) * 0.5f;
                }
            } else {
                if (r < M) {
                    dst[(size_t)r * Nw + c]     = acc[mt][nt][0] + b0;
                    dst[(size_t)r * Nw + c + 1] = acc[mt][nt][1] + b1;
                }
                if (r + 8 < M) {
                    dst[(size_t)(r + 8) * Nw + c]     = acc[mt][nt][2] + b0;
                    dst[(size_t)(r + 8) * Nw + c + 1] = acc[mt][nt][3] + b1;
                }
            }
        }
}

// ---------------------------------------------------------------------------
// tf32 GEMM (NN): C = A @ B + bias (used for output projection)
// ---------------------------------------------------------------------------
__global__ void gemm_nn_tf32(const float* __restrict__ A, const float* __restrict__ Bm,
                             const float* __restrict__ bias, float* __restrict__ C,
                             int M, int N, int K) {
    __shared__ __align__(16) uint32_t As[128][20];
    __shared__ __align__(16) uint32_t Bs[16][72];
    const int tid  = threadIdx.x;
    const int lane = tid & 31;
    const int warp = tid >> 5;
    const int g  = lane >> 2, t4 = lane & 3;
    const int wm = warp >> 1, wn = warp & 1;
    const int m0 = blockIdx.x * 128, n0 = blockIdx.y * 64;

    float acc[2][4][4] = {};

    for (int k0 = 0; k0 < K; k0 += 16) {
#pragma unroll
        for (int p = 0; p < 2; ++p) {
            int m  = p * 64 + (tid >> 2);
            int kk = (tid & 3) * 4;
            float4 a4 = make_float4(0.f, 0.f, 0.f, 0.f);
            int gm = m0 + m;
            if (gm < M) a4 = *reinterpret_cast<const float4*>(A + (size_t)gm * K + k0 + kk);
            uint4 u;
            u.x = f2tf32(a4.x); u.y = f2tf32(a4.y); u.z = f2tf32(a4.z); u.w = f2tf32(a4.w);
            *reinterpret_cast<uint4*>(&As[m][kk]) = u;
        }
        {
            int kr = tid >> 4, nn = (tid & 15) * 4;
            float4 b4 = make_float4(0.f, 0.f, 0.f, 0.f);
            if (n0 + nn < N)
                b4 = *reinterpret_cast<const float4*>(Bm + (size_t)(k0 + kr) * N + n0 + nn);
            uint4 u;
            u.x = f2tf32(b4.x); u.y = f2tf32(b4.y); u.z = f2tf32(b4.z); u.w = f2tf32(b4.w);
            *reinterpret_cast<uint4*>(&Bs[kr][nn]) = u;
        }
        __syncthreads();
#pragma unroll
        for (int ks = 0; ks < 2; ++ks) {
            const int kb = ks * 8;
            uint32_t af[2][4], bf[4][2];
#pragma unroll
            for (int mt = 0; mt < 2; ++mt) {
                int rb = wm * 32 + mt * 16;
                af[mt][0] = As[rb + g    ][kb + t4    ];
                af[mt][1] = As[rb + g + 8][kb + t4    ];
                af[mt][2] = As[rb + g    ][kb + t4 + 4];
                af[mt][3] = As[rb + g + 8][kb + t4 + 4];
            }
#pragma unroll
            for (int nt = 0; nt < 4; ++nt) {
                int cb = wn * 32 + nt * 8;
                bf[nt][0] = Bs[kb + t4    ][cb + g];
                bf[nt][1] = Bs[kb + t4 + 4][cb + g];
            }
#pragma unroll
            for (int mt = 0; mt < 2; ++mt)
#pragma unroll
                for (int nt = 0; nt < 4; ++nt)
                    mma_tf32(acc[mt][nt], af[mt], bf[nt]);
        }
        __syncthreads();
    }

#pragma unroll
    for (int mt = 0; mt < 2; ++mt)
#pragma unroll
        for (int nt = 0; nt < 4; ++nt) {
            int r = m0 + wm * 32 + mt * 16 + g;
            int c = n0 + wn * 32 + nt * 8 + t4 * 2;
            if (c < N) {
                float b0 = bias[c], b1 = bias[c + 1];
                if (r < M) {
                    C[(size_t)r * N + c]     = acc[mt][nt][0] + b0;
                    C[(size_t)r * N + c + 1] = acc[mt][nt][1] + b1;
                }
                if (r + 8 < M) {
                    C[(size_t)(r + 8) * N + c]     = acc[mt][nt][2] + b0;
                    C[(size_t)(r + 8) * N + c + 1] = acc[mt][nt][3] + b1;
                }
            }
        }
}

// ---------------------------------------------------------------------------
// tf32 GEMM (TN) for value projection; writes V in fp16.
// ---------------------------------------------------------------------------
__global__ void gemm_tn_tf32(const float* __restrict__ feat, const float* __restrict__ W,
                             const float* __restrict__ bias, int M /*HW*/, int sbase) {
    __shared__ __align__(16) uint32_t As[16][136];
    __shared__ __align__(16) uint32_t Bs[16][72];
    const int tid  = threadIdx.x;
    const int lane = tid & 31;
    const int warp = tid >> 5;
    const int g  = lane >> 2, t4 = lane & 3;
    const int wm = warp >> 1, wn = warp & 1;
    const int m0 = blockIdx.x * 128, n0 = blockIdx.y * 64;
    const int b  = blockIdx.z;
    const int K = D_, N = D_;

    const float* A = feat + (size_t)b * K * M;

    float acc[2][4][4] = {};

    for (int k0 = 0; k0 < K; k0 += 16) {
#pragma unroll
        for (int p = 0; p < 2; ++p) {
            int m = p * 64 + (tid & 15) * 4;
            int k = tid >> 4;
            float4 a4 = make_float4(0.f, 0.f, 0.f, 0.f);
            if (m0 + m < M)
                a4 = *reinterpret_cast<const float4*>(A + (size_t)(k0 + k) * M + m0 + m);
            uint4 u;
            u.x = f2tf32(a4.x); u.y = f2tf32(a4.y); u.z = f2tf32(a4.z); u.w = f2tf32(a4.w);
            *reinterpret_cast<uint4*>(&As[k][m]) = u;
        }
        {
            int kr = tid >> 4, nn = (tid & 15) * 4;
            float4 b4 = *reinterpret_cast<const float4*>(W + (size_t)(k0 + kr) * N + n0 + nn);
            uint4 u;
            u.x = f2tf32(b4.x); u.y = f2tf32(b4.y); u.z = f2tf32(b4.z); u.w = f2tf32(b4.w);
            *reinterpret_cast<uint4*>(&Bs[kr][nn]) = u;
        }
        __syncthreads();
#pragma unroll
        for (int ks = 0; ks < 2; ++ks) {
            const int kb = ks * 8;
            uint32_t af[2][4], bf[4][2];
#pragma unroll
            for (int mt = 0; mt < 2; ++mt) {
                int rb = wm * 32 + mt * 16;
                af[mt][0] = As[kb + t4    ][rb + g    ];
                af[mt][1] = As[kb + t4    ][rb + g + 8];
                af[mt][2] = As[kb + t4 + 4][rb + g    ];
                af[mt][3] = As[kb + t4 + 4][rb + g + 8];
            }
#pragma unroll
            for (int nt = 0; nt < 4; ++nt) {
                int cb = wn * 32 + nt * 8;
                bf[nt][0] = Bs[kb + t4    ][cb + g];
                bf[nt][1] = Bs[kb + t4 + 4][cb + g];
            }
#pragma unroll
            for (int mt = 0; mt < 2; ++mt)
#pragma unroll
                for (int nt = 0; nt < 4; ++nt)
                    mma_tf32(acc[mt][nt], af[mt], bf[nt]);
        }
        __syncthreads();
    }

#pragma unroll
    for (int mt = 0; mt < 2; ++mt)
#pragma unroll
        for (int nt = 0; nt < 4; ++nt) {
            int r = m0 + wm * 32 + mt * 16 + g;
            int c = n0 + wn * 32 + nt * 8 + t4 * 2;
            float b0 = bias[c], b1 = bias[c + 1];
            if (r < M) {
                size_t row = ((size_t)b * S_ + sbase + r) * D_;
                __half2 hv = __floats2half2_rn(acc[mt][nt][0] + b0, acc[mt][nt][1] + b1);
                *reinterpret_cast<__half2*>(&g_Vh[row + c]) = hv;
            }
            if (r + 8 < M) {
                size_t row = ((size_t)b * S_ + sbase + r + 8) * D_;
                __half2 hv = __floats2half2_rn(acc[mt][nt][2] + b0, acc[mt][nt][3] + b1);
                *reinterpret_cast<__half2*>(&g_Vh[row + c]) = hv;
            }
        }
}

// ---------------------------------------------------------------------------
// Softmax over 12 (level,point) logits: one thread per (bq, h); in place.
// ---------------------------------------------------------------------------
__global__ void softmax12(float* __restrict__ att) {
    int i = blockIdx.x * blockDim.x + threadIdx.x;
    if (i >= MQ_ * NH_) return;
    float* p = att + (size_t)(i >> 3) * 96 + (i & 7) * 12;
    float v[12], mx = -1e30f;
#pragma unroll
    for (int j = 0; j < 12; ++j) { v[j] = p[j]; mx = fmaxf(mx, v[j]); }
    float s = 0.f;
#pragma unroll
    for (int j = 0; j < 12; ++j) { v[j] = __expf(v[j] - mx); s += v[j]; }
    float inv = 1.f / s;
#pragma unroll
    for (int j = 0; j < 12; ++j) p[j] = v[j] * inv;
}

// ---------------------------------------------------------------------------
// Sampling: warp per (bq, pass); branch-free clamped loads (4 unconditional
// LDGs per point -> full MLP overlap of L2 latency), OOB masked by weights.
// ---------------------------------------------------------------------------
__global__ void sample_kernel(const float* __restrict__ ref) {
    const int gw   = (blockIdx.x * blockDim.x + threadIdx.x) >> 5;
    const int lane = threadIdx.x & 31;
    if (gw >= MQ_ * 2) return;

    const int bq   = gw >> 1;
    const int pass = gw & 1;
    const int b    = bq / Q_;
    const int grp  = lane >> 3;
    const int cl   = (lane & 7) * 4;

    const float rx = __ldg(ref + (size_t)bq * 2 + 0);
    const float ry = __ldg(ref + (size_t)bq * 2 + 1);

    const int Wls[3] = {80, 40, 20};
    const int bas[3] = {0, 6400, 8000};

    const int h = grp + pass * 4;
    const float* offp = g_OFF + (size_t)bq * 192 + h * 24;
    const float* attp = g_ATT + (size_t)bq * 96 + h * 12;
    const __half* Vb  = g_Vh + (size_t)b * S_ * D_ + h * HD_ + cl;

    float4 acc0 = make_float4(0.f, 0.f, 0.f, 0.f);
    float4 acc1 = make_float4(0.f, 0.f, 0.f, 0.f);

#pragma unroll
    for (int l = 0; l < NL_; ++l) {
        const int Wl = Wls[l], base = bas[l];
        const float Wlf = (float)Wl;
#pragma unroll
        for (int p = 0; p < NP_; ++p) {
            float4& acc = (p & 1) ? acc1 : acc0;
            const float ox = __ldg(offp + (l * 4 + p) * 2 + 0);
            const float oy = __ldg(offp + (l * 4 + p) * 2 + 1);
            const float w  = __ldg(attp + l * 4 + p);
            const float ix = (rx + ox) * Wlf - 0.5f;
            const float iy = (ry + oy) * Wlf - 0.5f;
            const float x0f = floorf(ix), y0f = floorf(iy);
            const int x0 = (int)x0f, y0 = (int)y0f;
            const float fx = ix - x0f, fy = iy - y0f;

            // OOB -> zero weight; index clamped (always safe to load)
            const float mx0 = (x0 >= 0     && x0 < Wl)     ? (1.f - fx) : 0.f;
            const float mx1 = (x0 + 1 >= 0 && x0 + 1 < Wl) ? fx         : 0.f;
            const float my0 = (y0 >= 0     && y0 < Wl)     ? (1.f - fy) : 0.f;
            const float my1 = (y0 + 1 >= 0 && y0 + 1 < Wl) ? fy         : 0.f;
            const float w00 = w * mx0 * my0;
            const float w01 = w * mx1 * my0;
            const float w10 = w * mx0 * my1;
            const float w11 = w * mx1 * my1;

            const int xc0 = min(max(x0, 0), Wl - 1);
            const int xc1 = min(max(x0 + 1, 0), Wl - 1);
            const int yc0 = min(max(y0, 0), Wl - 1);
            const int yc1 = min(max(y0 + 1, 0), Wl - 1);

            // 4 unconditional loads, issued back-to-back
            uint2 u00 = *reinterpret_cast<const uint2*>(Vb + (size_t)(base + yc0 * Wl + xc0) * D_);
            uint2 u01 = *reinterpret_cast<const uint2*>(Vb + (size_t)(base + yc0 * Wl + xc1) * D_);
            uint2 u10 = *reinterpret_cast<const uint2*>(Vb + (size_t)(base + yc1 * Wl + xc0) * D_);
            uint2 u11 = *reinterpret_cast<const uint2*>(Vb + (size_t)(base + yc1 * Wl + xc1) * D_);

#define ACC_U(u, wgt)                                                          \
            {                                                                  \
                float2 f0 = __half22float2(*reinterpret_cast<__half2*>(&u.x)); \
                float2 f1 = __half22float2(*reinterpret_cast<__half2*>(&u.y)); \
                acc.x = fmaf(wgt, f0.x, acc.x); acc.y = fmaf(wgt, f0.y, acc.y);\
                acc.z = fmaf(wgt, f1.x, acc.z); acc.w = fmaf(wgt, f1.y, acc.w);\
            }
            ACC_U(u00, w00)
            ACC_U(u01, w01)
            ACC_U(u10, w10)
            ACC_U(u11, w11)
#undef ACC_U
        }
    }

    float4 acc;
    acc.x = acc0.x + acc1.x; acc.y = acc0.y + acc1.y;
    acc.z = acc0.z + acc1.z; acc.w = acc0.w + acc1.w;
    *reinterpret_cast<float4*>(g_MID + (size_t)bq * D_ + h * HD_ + cl) = acc;
}

// ---------------------------------------------------------------------------
// Launch
// ---------------------------------------------------------------------------
extern "C" void kernel_launch(void* const* d_in, const int* in_sizes, int n_in,
                              void* d_out, int out_size) {
    const float* query = (const float*)d_in[0];
    const float* feat0 = (const float*)d_in[1];
    const float* feat1 = (const float*)d_in[2];
    const float* feat2 = (const float*)d_in[3];
    const float* refp  = (const float*)d_in[4];
    const float* W_off = (const float*)d_in[5];
    const float* b_off = (const float*)d_in[6];
    const float* W_att = (const float*)d_in[7];
    const float* b_att = (const float*)d_in[8];
    const float* W_val = (const float*)d_in[9];
    const float* b_val = (const float*)d_in[10];
    const float* W_out = (const float*)d_in[11];
    const float* b_out = (const float*)d_in[12];
    float* out = (float*)d_out;

    float* pATT; cudaGetSymbolAddress((void**)&pATT, g_ATT);
    float* pMID; cudaGetSymbolAddress((void**)&pMID, g_MID);

    dim3 blk(256);

    // 0) pre-split query to bf16 hi/lo
    split_query<<<(MQ_ * D_ / 4 + 255) / 256, 256>>>(query);

    // 1) value projection per level (tf32 tensor cores, fp16 V output)
    gemm_tn_tf32<<<dim3(50, 4, B_), blk>>>(feat0, W_val, b_val, 6400, 0);
    gemm_tn_tf32<<<dim3(13, 4, B_), blk>>>(feat1, W_val, b_val, 1600, 6400);
    gemm_tn_tf32<<<dim3( 4, 4, B_), blk>>>(feat2, W_val, b_val,  400, 8000);

    // 2) fused offset+attn logits (3xBF16, N=288)
    gemm_off_att_3xbf16<<<dim3((MQ_ + 127) / 128, 5), blk>>>(W_off, b_off, W_att, b_att);

    // 3) softmax over attn logits
    softmax12<<<(MQ_ * NH_ + 255) / 256, 256>>>(pATT);

    // 4) bilinear sampling -> MID
    sample_kernel<<<(MQ_ * 2 + 7) / 8, 256>>>(refp);

    // 5) output projection (tf32)
    gemm_nn_tf32<<<dim3((MQ_ + 127) / 128, 4), blk>>>(pMID, W_out, b_out, out, MQ_, D_, D_);
}

// round 10
// speedup vs baseline: 1.2142x; 1.2142x over previous
#include <cuda_runtime.h>
#include <cuda_fp16.h>
#include <cuda_bf16.h>
#include <cstdint>

// ---------------------------------------------------------------------------
// MultiScaleDETR deformable attention.
// B=4, Q=8400, D=256, nH=8, hd=32, L=3 (80x80,40x40,20x20), P=4.
// tf32 GEMMs for value/output; 3xBF16 split GEMM for offsets; fp16 V.
// Single merged valproj launch; valproj overlapped with offset/attn GEMMs
// on a side stream (graph-capturable event fork/join).
// ---------------------------------------------------------------------------

#define B_    4
#define Q_    8400
#define D_    256
#define NH_   8
#define HD_   32
#define NL_   3
#define NP_   4
#define S_    8400
#define MQ_   (B_ * Q_)      // 33600

__device__ __half g_Vh [B_ * S_ * D_];  // value projection, fp16
__device__ float  g_OFF[MQ_ * 192];     // tanh(offset_logit)*0.5
__device__ float  g_ATT[MQ_ * 96];      // attn logits -> softmaxed in place
__device__ float  g_MID[MQ_ * D_];      // attention output pre-W_out

// ---------------------------------------------------------------------------
// mma helpers
// ---------------------------------------------------------------------------
__device__ __forceinline__ uint32_t f2tf32(float f) {
    uint32_t u;
    asm("cvt.rna.tf32.f32 %0, %1;" : "=r"(u) : "f"(f));
    return u;
}

__device__ __forceinline__ void mma_tf32(float* d, const uint32_t* a, const uint32_t* b) {
    asm volatile(
        "mma.sync.aligned.m16n8k8.row.col.f32.tf32.tf32.f32 "
        "{%0,%1,%2,%3}, {%4,%5,%6,%7}, {%8,%9}, {%0,%1,%2,%3};\n"
        : "+f"(d[0]), "+f"(d[1]), "+f"(d[2]), "+f"(d[3])
        : "r"(a[0]), "r"(a[1]), "r"(a[2]), "r"(a[3]), "r"(b[0]), "r"(b[1]));
}

__device__ __forceinline__ void mma_bf16(float* d, const uint32_t* a, const uint32_t* b) {
    asm volatile(
        "mma.sync.aligned.m16n8k16.row.col.f32.bf16.bf16.f32 "
        "{%0,%1,%2,%3}, {%4,%5,%6,%7}, {%8,%9}, {%0,%1,%2,%3};\n"
        : "+f"(d[0]), "+f"(d[1]), "+f"(d[2]), "+f"(d[3])
        : "r"(a[0]), "r"(a[1]), "r"(a[2]), "r"(a[3]), "r"(b[0]), "r"(b[1]));
}

__device__ __forceinline__ uint32_t pack_bf16(__nv_bfloat16 a, __nv_bfloat16 b) {
    __nv_bfloat162 h; h.x = a; h.y = b;
    return *reinterpret_cast<uint32_t*>(&h);
}

// ---------------------------------------------------------------------------
// tf32 GEMM (NN): C = A @ B + bias (attn logits, output projection)
// ---------------------------------------------------------------------------
__global__ void gemm_nn_tf32(const float* __restrict__ A, const float* __restrict__ Bm,
                             const float* __restrict__ bias, float* __restrict__ C,
                             int M, int N, int K) {
    __shared__ __align__(16) uint32_t As[128][20];
    __shared__ __align__(16) uint32_t Bs[16][72];
    const int tid  = threadIdx.x;
    const int lane = tid & 31;
    const int warp = tid >> 5;
    const int g  = lane >> 2, t4 = lane & 3;
    const int wm = warp >> 1, wn = warp & 1;
    const int m0 = blockIdx.x * 128, n0 = blockIdx.y * 64;

    float acc[2][4][4] = {};

    for (int k0 = 0; k0 < K; k0 += 16) {
#pragma unroll
        for (int p = 0; p < 2; ++p) {
            int m  = p * 64 + (tid >> 2);
            int kk = (tid & 3) * 4;
            float4 a4 = make_float4(0.f, 0.f, 0.f, 0.f);
            int gm = m0 + m;
            if (gm < M) a4 = *reinterpret_cast<const float4*>(A + (size_t)gm * K + k0 + kk);
            uint4 u;
            u.x = f2tf32(a4.x); u.y = f2tf32(a4.y); u.z = f2tf32(a4.z); u.w = f2tf32(a4.w);
            *reinterpret_cast<uint4*>(&As[m][kk]) = u;
        }
        {
            int kr = tid >> 4, nn = (tid & 15) * 4;
            float4 b4 = make_float4(0.f, 0.f, 0.f, 0.f);
            if (n0 + nn < N)
                b4 = *reinterpret_cast<const float4*>(Bm + (size_t)(k0 + kr) * N + n0 + nn);
            uint4 u;
            u.x = f2tf32(b4.x); u.y = f2tf32(b4.y); u.z = f2tf32(b4.z); u.w = f2tf32(b4.w);
            *reinterpret_cast<uint4*>(&Bs[kr][nn]) = u;
        }
        __syncthreads();
#pragma unroll
        for (int ks = 0; ks < 2; ++ks) {
            const int kb = ks * 8;
            uint32_t af[2][4], bf[4][2];
#pragma unroll
            for (int mt = 0; mt < 2; ++mt) {
                int rb = wm * 32 + mt * 16;
                af[mt][0] = As[rb + g    ][kb + t4    ];
                af[mt][1] = As[rb + g + 8][kb + t4    ];
                af[mt][2] = As[rb + g    ][kb + t4 + 4];
                af[mt][3] = As[rb + g + 8][kb + t4 + 4];
            }
#pragma unroll
            for (int nt = 0; nt < 4; ++nt) {
                int cb = wn * 32 + nt * 8;
                bf[nt][0] = Bs[kb + t4    ][cb + g];
                bf[nt][1] = Bs[kb + t4 + 4][cb + g];
            }
#pragma unroll
            for (int mt = 0; mt < 2; ++mt)
#pragma unroll
                for (int nt = 0; nt < 4; ++nt)
                    mma_tf32(acc[mt][nt], af[mt], bf[nt]);
        }
        __syncthreads();
    }

#pragma unroll
    for (int mt = 0; mt < 2; ++mt)
#pragma unroll
        for (int nt = 0; nt < 4; ++nt) {
            int r = m0 + wm * 32 + mt * 16 + g;
            int c = n0 + wn * 32 + nt * 8 + t4 * 2;
            if (c < N) {
                float b0 = bias[c], b1 = bias[c + 1];
                if (r < M) {
                    C[(size_t)r * N + c]     = acc[mt][nt][0] + b0;
                    C[(size_t)r * N + c + 1] = acc[mt][nt][1] + b1;
                }
                if (r + 8 < M) {
                    C[(size_t)(r + 8) * N + c]     = acc[mt][nt][2] + b0;
                    C[(size_t)(r + 8) * N + c + 1] = acc[mt][nt][3] + b1;
                }
            }
        }
}

// ---------------------------------------------------------------------------
// 3xBF16 split GEMM (NN) with tanh(x)*0.5 epilogue (offset logits).
// ---------------------------------------------------------------------------
__global__ void gemm_nn_tanh_3xbf16(const float* __restrict__ A, const float* __restrict__ Bm,
                                    const float* __restrict__ bias, float* __restrict__ C,
                                    int M, int N, int K) {
    __shared__ __align__(16) uint32_t AsH[128][12];
    __shared__ __align__(16) uint32_t AsL[128][12];
    __shared__ __align__(16) uint32_t BsH[8][72];
    __shared__ __align__(16) uint32_t BsL[8][72];
    const int tid  = threadIdx.x;
    const int lane = tid & 31;
    const int warp = tid >> 5;
    const int g  = lane >> 2, t4 = lane & 3;
    const int wm = warp >> 1, wn = warp & 1;
    const int m0 = blockIdx.x * 128, n0 = blockIdx.y * 64;

    float acc[2][4][4] = {};

    for (int k0 = 0; k0 < K; k0 += 16) {
#pragma unroll
        for (int p = 0; p < 2; ++p) {
            int m   = p * 64 + (tid >> 2);
            int kk4 = (tid & 3) * 4;
            float4 a4 = make_float4(0.f, 0.f, 0.f, 0.f);
            int gm = m0 + m;
            if (gm < M) a4 = *reinterpret_cast<const float4*>(A + (size_t)gm * K + k0 + kk4);
            __nv_bfloat16 h0 = __float2bfloat16_rn(a4.x);
            __nv_bfloat16 h1 = __float2bfloat16_rn(a4.y);
            __nv_bfloat16 h2 = __float2bfloat16_rn(a4.z);
            __nv_bfloat16 h3 = __float2bfloat16_rn(a4.w);
            __nv_bfloat16 l0 = __float2bfloat16_rn(a4.x - __bfloat162float(h0));
            __nv_bfloat16 l1 = __float2bfloat16_rn(a4.y - __bfloat162float(h1));
            __nv_bfloat16 l2 = __float2bfloat16_rn(a4.z - __bfloat162float(h2));
            __nv_bfloat16 l3 = __float2bfloat16_rn(a4.w - __bfloat162float(h3));
            int kp = (tid & 3) * 2;
            AsH[m][kp]     = pack_bf16(h0, h1);
            AsH[m][kp + 1] = pack_bf16(h2, h3);
            AsL[m][kp]     = pack_bf16(l0, l1);
            AsL[m][kp + 1] = pack_bf16(l2, l3);
        }
        {
            int n  = tid & 63;
            int k2 = tid >> 6;
#pragma unroll
            for (int q = 0; q < 2; ++q) {
                int kk = k2 + q * 4;
                float v0 = Bm[(size_t)(k0 + 2 * kk)     * N + n0 + n];
                float v1 = Bm[(size_t)(k0 + 2 * kk + 1) * N + n0 + n];
                __nv_bfloat16 h0 = __float2bfloat16_rn(v0);
                __nv_bfloat16 h1 = __float2bfloat16_rn(v1);
                __nv_bfloat16 l0 = __float2bfloat16_rn(v0 - __bfloat162float(h0));
                __nv_bfloat16 l1 = __float2bfloat16_rn(v1 - __bfloat162float(h1));
                BsH[kk][n] = pack_bf16(h0, h1);
                BsL[kk][n] = pack_bf16(l0, l1);
            }
        }
        __syncthreads();

        uint32_t afH[2][4], afL[2][4], bfH[4][2], bfL[4][2];
#pragma unroll
        for (int mt = 0; mt < 2; ++mt) {
            int rb = wm * 32 + mt * 16;
            afH[mt][0] = AsH[rb + g    ][t4    ];
            afH[mt][1] = AsH[rb + g + 8][t4    ];
            afH[mt][2] = AsH[rb + g    ][t4 + 4];
            afH[mt][3] = AsH[rb + g + 8][t4 + 4];
            afL[mt][0] = AsL[rb + g    ][t4    ];
            afL[mt][1] = AsL[rb + g + 8][t4    ];
            afL[mt][2] = AsL[rb + g    ][t4 + 4];
            afL[mt][3] = AsL[rb + g + 8][t4 + 4];
        }
#pragma unroll
        for (int nt = 0; nt < 4; ++nt) {
            int cb = wn * 32 + nt * 8;
            bfH[nt][0] = BsH[t4    ][cb + g];
            bfH[nt][1] = BsH[t4 + 4][cb + g];
            bfL[nt][0] = BsL[t4    ][cb + g];
            bfL[nt][1] = BsL[t4 + 4][cb + g];
        }
#pragma unroll
        for (int mt = 0; mt < 2; ++mt)
#pragma unroll
            for (int nt = 0; nt < 4; ++nt)
                mma_bf16(acc[mt][nt], afH[mt], bfL[nt]);
#pragma unroll
        for (int mt = 0; mt < 2; ++mt)
#pragma unroll
            for (int nt = 0; nt < 4; ++nt)
                mma_bf16(acc[mt][nt], afL[mt], bfH[nt]);
#pragma unroll
        for (int mt = 0; mt < 2; ++mt)
#pragma unroll
            for (int nt = 0; nt < 4; ++nt)
                mma_bf16(acc[mt][nt], afH[mt], bfH[nt]);
        __syncthreads();
    }

#pragma unroll
    for (int mt = 0; mt < 2; ++mt)
#pragma unroll
        for (int nt = 0; nt < 4; ++nt) {
            int r = m0 + wm * 32 + mt * 16 + g;
            int c = n0 + wn * 32 + nt * 8 + t4 * 2;
            float b0 = bias[c], b1 = bias[c + 1];
            if (r < M) {
                C[(size_t)r * N + c]     = tanhf(acc[mt][nt][0] + b0) * 0.5f;
                C[(size_t)r * N + c + 1] = tanhf(acc[mt][nt][1] + b1) * 0.5f;
            }
            if (r + 8 < M) {
                C[(size_t)(r + 8) * N + c]     = tanhf(acc[mt][nt][2] + b0) * 0.5f;
                C[(size_t)(r + 8) * N + c + 1] = tanhf(acc[mt][nt][3] + b1) * 0.5f;
            }
        }
}

// ---------------------------------------------------------------------------
// Merged tf32 GEMM (TN) value projection: all 3 levels in ONE launch.
// blockIdx.x in [0,67): [0,50)->lvl0, [50,63)->lvl1, [63,67)->lvl2.
// Writes V in fp16.
// ---------------------------------------------------------------------------
__global__ void gemm_tn_tf32_all(const float* __restrict__ f0, const float* __restrict__ f1,
                                 const float* __restrict__ f2, const float* __restrict__ W,
                                 const float* __restrict__ bias) {
    __shared__ __align__(16) uint32_t As[16][136];
    __shared__ __align__(16) uint32_t Bs[16][72];
    const int tid  = threadIdx.x;
    const int lane = tid & 31;
    const int warp = tid >> 5;
    const int g  = lane >> 2, t4 = lane & 3;
    const int wm = warp >> 1, wn = warp & 1;
    const int bx = blockIdx.x;
    const int n0 = blockIdx.y * 64;
    const int b  = blockIdx.z;
    const int K = D_, N = D_;

    const float* feat; int M, sbase, mblk;
    if (bx < 50)      { feat = f0; M = 6400; sbase = 0;    mblk = bx; }
    else if (bx < 63) { feat = f1; M = 1600; sbase = 6400; mblk = bx - 50; }
    else              { feat = f2; M = 400;  sbase = 8000; mblk = bx - 63; }
    const int m0 = mblk * 128;

    const float* A = feat + (size_t)b * K * M;

    float acc[2][4][4] = {};

    for (int k0 = 0; k0 < K; k0 += 16) {
#pragma unroll
        for (int p = 0; p < 2; ++p) {
            int m = p * 64 + (tid & 15) * 4;
            int k = tid >> 4;
            float4 a4 = make_float4(0.f, 0.f, 0.f, 0.f);
            if (m0 + m < M)
                a4 = *reinterpret_cast<const float4*>(A + (size_t)(k0 + k) * M + m0 + m);
            uint4 u;
            u.x = f2tf32(a4.x); u.y = f2tf32(a4.y); u.z = f2tf32(a4.z); u.w = f2tf32(a4.w);
            *reinterpret_cast<uint4*>(&As[k][m]) = u;
        }
        {
            int kr = tid >> 4, nn = (tid & 15) * 4;
            float4 b4 = *reinterpret_cast<const float4*>(W + (size_t)(k0 + kr) * N + n0 + nn);
            uint4 u;
            u.x = f2tf32(b4.x); u.y = f2tf32(b4.y); u.z = f2tf32(b4.z); u.w = f2tf32(b4.w);
            *reinterpret_cast<uint4*>(&Bs[kr][nn]) = u;
        }
        __syncthreads();
#pragma unroll
        for (int ks = 0; ks < 2; ++ks) {
            const int kb = ks * 8;
            uint32_t af[2][4], bf[4][2];
#pragma unroll
            for (int mt = 0; mt < 2; ++mt) {
                int rb = wm * 32 + mt * 16;
                af[mt][0] = As[kb + t4    ][rb + g    ];
                af[mt][1] = As[kb + t4    ][rb + g + 8];
                af[mt][2] = As[kb + t4 + 4][rb + g    ];
                af[mt][3] = As[kb + t4 + 4][rb + g + 8];
            }
#pragma unroll
            for (int nt = 0; nt < 4; ++nt) {
                int cb = wn * 32 + nt * 8;
                bf[nt][0] = Bs[kb + t4    ][cb + g];
                bf[nt][1] = Bs[kb + t4 + 4][cb + g];
            }
#pragma unroll
            for (int mt = 0; mt < 2; ++mt)
#pragma unroll
                for (int nt = 0; nt < 4; ++nt)
                    mma_tf32(acc[mt][nt], af[mt], bf[nt]);
        }
        __syncthreads();
    }

#pragma unroll
    for (int mt = 0; mt < 2; ++mt)
#pragma unroll
        for (int nt = 0; nt < 4; ++nt) {
            int r = m0 + wm * 32 + mt * 16 + g;
            int c = n0 + wn * 32 + nt * 8 + t4 * 2;
            float b0 = bias[c], b1 = bias[c + 1];
            if (r < M) {
                size_t row = ((size_t)b * S_ + sbase + r) * D_;
                __half2 hv = __floats2half2_rn(acc[mt][nt][0] + b0, acc[mt][nt][1] + b1);
                *reinterpret_cast<__half2*>(&g_Vh[row + c]) = hv;
            }
            if (r + 8 < M) {
                size_t row = ((size_t)b * S_ + sbase + r + 8) * D_;
                __half2 hv = __floats2half2_rn(acc[mt][nt][2] + b0, acc[mt][nt][3] + b1);
                *reinterpret_cast<__half2*>(&g_Vh[row + c]) = hv;
            }
        }
}

// ---------------------------------------------------------------------------
// Softmax over 12 (level,point) logits: one thread per (bq, h); in place.
// ---------------------------------------------------------------------------
__global__ void softmax12(float* __restrict__ att) {
    int i = blockIdx.x * blockDim.x + threadIdx.x;
    if (i >= MQ_ * NH_) return;
    float* p = att + (size_t)(i >> 3) * 96 + (i & 7) * 12;
    float v[12], mx = -1e30f;
#pragma unroll
    for (int j = 0; j < 12; ++j) { v[j] = p[j]; mx = fmaxf(mx, v[j]); }
    float s = 0.f;
#pragma unroll
    for (int j = 0; j < 12; ++j) { v[j] = __expf(v[j] - mx); s += v[j]; }
    float inv = 1.f / s;
#pragma unroll
    for (int j = 0; j < 12; ++j) p[j] = v[j] * inv;
}

// ---------------------------------------------------------------------------
// Sampling (R8 version): warp per (bq, pass), predicated corner loads,
// dual accumulators.
// ---------------------------------------------------------------------------
__global__ void sample_kernel(const float* __restrict__ ref) {
    const int gw   = (blockIdx.x * blockDim.x + threadIdx.x) >> 5;
    const int lane = threadIdx.x & 31;
    if (gw >= MQ_ * 2) return;

    const int bq   = gw >> 1;
    const int pass = gw & 1;
    const int b    = bq / Q_;
    const int grp  = lane >> 3;
    const int cl   = (lane & 7) * 4;

    const float rx = __ldg(ref + (size_t)bq * 2 + 0);
    const float ry = __ldg(ref + (size_t)bq * 2 + 1);

    const int Wls[3] = {80, 40, 20};
    const int bas[3] = {0, 6400, 8000};

    const int h = grp + pass * 4;
    const float* offp = g_OFF + (size_t)bq * 192 + h * 24;
    const float* attp = g_ATT + (size_t)bq * 96 + h * 12;
    const __half* Vb  = g_Vh + (size_t)b * S_ * D_ + h * HD_ + cl;

    float4 acc0 = make_float4(0.f, 0.f, 0.f, 0.f);
    float4 acc1 = make_float4(0.f, 0.f, 0.f, 0.f);

#pragma unroll
    for (int l = 0; l < NL_; ++l) {
        const int Wl = Wls[l], base = bas[l];
        const float Wlf = (float)Wl;
#pragma unroll
        for (int p = 0; p < NP_; ++p) {
            float4& acc = (p & 1) ? acc1 : acc0;
            const float ox = __ldg(offp + (l * 4 + p) * 2 + 0);
            const float oy = __ldg(offp + (l * 4 + p) * 2 + 1);
            const float w  = __ldg(attp + l * 4 + p);
            const float ix = (rx + ox) * Wlf - 0.5f;
            const float iy = (ry + oy) * Wlf - 0.5f;
            const float x0f = floorf(ix), y0f = floorf(iy);
            const int x0 = (int)x0f, y0 = (int)y0f;
            const float fx = ix - x0f, fy = iy - y0f;
            const float w00 = w * (1.f - fx) * (1.f - fy);
            const float w01 = w * fx * (1.f - fy);
            const float w10 = w * (1.f - fx) * fy;
            const float w11 = w * fx * fy;

            const bool xin0 = (x0 >= 0) && (x0 < Wl);
            const bool xin1 = (x0 + 1 >= 0) && (x0 + 1 < Wl);
            const bool yin0 = (y0 >= 0) && (y0 < Wl);
            const bool yin1 = (y0 + 1 >= 0) && (y0 + 1 < Wl);

#define ACC_CORNER(cond, idx, wgt)                                              \
            if (cond) {                                                         \
                uint2 u = *reinterpret_cast<const uint2*>(Vb + (size_t)(idx) * D_); \
                float2 f0 = __half22float2(*reinterpret_cast<__half2*>(&u.x));  \
                float2 f1 = __half22float2(*reinterpret_cast<__half2*>(&u.y));  \
                acc.x = fmaf(wgt, f0.x, acc.x); acc.y = fmaf(wgt, f0.y, acc.y); \
                acc.z = fmaf(wgt, f1.x, acc.z); acc.w = fmaf(wgt, f1.y, acc.w); \
            }

            ACC_CORNER(xin0 && yin0, base + y0 * Wl + x0,           w00)
            ACC_CORNER(xin1 && yin0, base + y0 * Wl + x0 + 1,       w01)
            ACC_CORNER(xin0 && yin1, base + (y0 + 1) * Wl + x0,     w10)
            ACC_CORNER(xin1 && yin1, base + (y0 + 1) * Wl + x0 + 1, w11)
#undef ACC_CORNER
        }
    }

    float4 acc;
    acc.x = acc0.x + acc1.x; acc.y = acc0.y + acc1.y;
    acc.z = acc0.z + acc1.z; acc.w = acc0.w + acc1.w;
    *reinterpret_cast<float4*>(g_MID + (size_t)bq * D_ + h * HD_ + cl) = acc;
}

// ---------------------------------------------------------------------------
// Launch: valproj on side stream, overlapped with offset/attn/softmax chain.
// ---------------------------------------------------------------------------
extern "C" void kernel_launch(void* const* d_in, const int* in_sizes, int n_in,
                              void* d_out, int out_size) {
    const float* query = (const float*)d_in[0];
    const float* feat0 = (const float*)d_in[1];
    const float* feat1 = (const float*)d_in[2];
    const float* feat2 = (const float*)d_in[3];
    const float* refp  = (const float*)d_in[4];
    const float* W_off = (const float*)d_in[5];
    const float* b_off = (const float*)d_in[6];
    const float* W_att = (const float*)d_in[7];
    const float* b_att = (const float*)d_in[8];
    const float* W_val = (const float*)d_in[9];
    const float* b_val = (const float*)d_in[10];
    const float* W_out = (const float*)d_in[11];
    const float* b_out = (const float*)d_in[12];
    float* out = (float*)d_out;

    float* pOFF; cudaGetSymbolAddress((void**)&pOFF, g_OFF);
    float* pATT; cudaGetSymbolAddress((void**)&pATT, g_ATT);
    float* pMID; cudaGetSymbolAddress((void**)&pMID, g_MID);

    // persistent side stream + events (host objects, created once; identical
    // GPU work every call)
    static cudaStream_t s1 = nullptr;
    static cudaEvent_t evRoot = nullptr, evV = nullptr;
    if (s1 == nullptr) {
        cudaStreamCreateWithFlags(&s1, cudaStreamNonBlocking);
        cudaEventCreateWithFlags(&evRoot, cudaEventDisableTiming);
        cudaEventCreateWithFlags(&evV,    cudaEventDisableTiming);
    }

    dim3 blk(256);

    // fork: side stream joins the captured (default) stream
    cudaEventRecord(evRoot, 0);
    cudaStreamWaitEvent(s1, evRoot, 0);

    // side stream: merged value projection (all levels, one launch)
    gemm_tn_tf32_all<<<dim3(67, 4, B_), blk, 0, s1>>>(feat0, feat1, feat2, W_val, b_val);
    cudaEventRecord(evV, s1);

    // main stream (concurrent): offset logits + attn logits + softmax
    gemm_nn_tanh_3xbf16<<<dim3((MQ_ + 127) / 128, 3), blk>>>(query, W_off, b_off, pOFF, MQ_, 192, D_);
    gemm_nn_tf32<<<dim3((MQ_ + 127) / 128, 2), blk>>>(query, W_att, b_att, pATT, MQ_, 96, D_);
    softmax12<<<(MQ_ * NH_ + 255) / 256, 256>>>(pATT);

    // join: sampler needs V + OFF + ATT
    cudaStreamWaitEvent(0, evV, 0);

    // bilinear sampling -> MID
    sample_kernel<<<(MQ_ * 2 + 7) / 8, 256>>>(refp);

    // output projection (tf32)
    gemm_nn_tf32<<<dim3((MQ_ + 127) / 128, 4), blk>>>(pMID, W_out, b_out, out, MQ_, D_, D_);
}

// round 11
// speedup vs baseline: 1.2630x; 1.0402x over previous
#include <cuda_runtime.h>
#include <cuda_fp16.h>
#include <cuda_bf16.h>
#include <cstdint>

// ---------------------------------------------------------------------------
// MultiScaleDETR deformable attention.
// B=4, Q=8400, D=256, nH=8, hd=32, L=3 (80x80,40x40,20x20), P=4.
// tf32 GEMMs for value/output; fused 3xBF16 split GEMM (N=288) for
// offset+attn logits; softmax fused into the fp16-gather sampler;
// valproj overlapped on a side stream.
// ---------------------------------------------------------------------------

#define B_    4
#define Q_    8400
#define D_    256
#define NH_   8
#define HD_   32
#define NL_   3
#define NP_   4
#define S_    8400
#define MQ_   (B_ * Q_)      // 33600

__device__ __half g_Vh [B_ * S_ * D_];  // value projection, fp16
__device__ float  g_OFF[MQ_ * 192];     // tanh(offset_logit)*0.5
__device__ float  g_ATT[MQ_ * 96];      // raw attn logits (softmax in sampler)
__device__ float  g_MID[MQ_ * D_];      // attention output pre-W_out

// ---------------------------------------------------------------------------
// mma helpers
// ---------------------------------------------------------------------------
__device__ __forceinline__ uint32_t f2tf32(float f) {
    uint32_t u;
    asm("cvt.rna.tf32.f32 %0, %1;" : "=r"(u) : "f"(f));
    return u;
}

__device__ __forceinline__ void mma_tf32(float* d, const uint32_t* a, const uint32_t* b) {
    asm volatile(
        "mma.sync.aligned.m16n8k8.row.col.f32.tf32.tf32.f32 "
        "{%0,%1,%2,%3}, {%4,%5,%6,%7}, {%8,%9}, {%0,%1,%2,%3};\n"
        : "+f"(d[0]), "+f"(d[1]), "+f"(d[2]), "+f"(d[3])
        : "r"(a[0]), "r"(a[1]), "r"(a[2]), "r"(a[3]), "r"(b[0]), "r"(b[1]));
}

__device__ __forceinline__ void mma_bf16(float* d, const uint32_t* a, const uint32_t* b) {
    asm volatile(
        "mma.sync.aligned.m16n8k16.row.col.f32.bf16.bf16.f32 "
        "{%0,%1,%2,%3}, {%4,%5,%6,%7}, {%8,%9}, {%0,%1,%2,%3};\n"
        : "+f"(d[0]), "+f"(d[1]), "+f"(d[2]), "+f"(d[3])
        : "r"(a[0]), "r"(a[1]), "r"(a[2]), "r"(a[3]), "r"(b[0]), "r"(b[1]));
}

__device__ __forceinline__ uint32_t pack_bf16(__nv_bfloat16 a, __nv_bfloat16 b) {
    __nv_bfloat162 h; h.x = a; h.y = b;
    return *reinterpret_cast<uint32_t*>(&h);
}

// ---------------------------------------------------------------------------
// tf32 GEMM (NN): C = A @ B + bias (output projection)
// ---------------------------------------------------------------------------
__global__ void gemm_nn_tf32(const float* __restrict__ A, const float* __restrict__ Bm,
                             const float* __restrict__ bias, float* __restrict__ C,
                             int M, int N, int K) {
    __shared__ __align__(16) uint32_t As[128][20];
    __shared__ __align__(16) uint32_t Bs[16][72];
    const int tid  = threadIdx.x;
    const int lane = tid & 31;
    const int warp = tid >> 5;
    const int g  = lane >> 2, t4 = lane & 3;
    const int wm = warp >> 1, wn = warp & 1;
    const int m0 = blockIdx.x * 128, n0 = blockIdx.y * 64;

    float acc[2][4][4] = {};

    for (int k0 = 0; k0 < K; k0 += 16) {
#pragma unroll
        for (int p = 0; p < 2; ++p) {
            int m  = p * 64 + (tid >> 2);
            int kk = (tid & 3) * 4;
            float4 a4 = make_float4(0.f, 0.f, 0.f, 0.f);
            int gm = m0 + m;
            if (gm < M) a4 = *reinterpret_cast<const float4*>(A + (size_t)gm * K + k0 + kk);
            uint4 u;
            u.x = f2tf32(a4.x); u.y = f2tf32(a4.y); u.z = f2tf32(a4.z); u.w = f2tf32(a4.w);
            *reinterpret_cast<uint4*>(&As[m][kk]) = u;
        }
        {
            int kr = tid >> 4, nn = (tid & 15) * 4;
            float4 b4 = make_float4(0.f, 0.f, 0.f, 0.f);
            if (n0 + nn < N)
                b4 = *reinterpret_cast<const float4*>(Bm + (size_t)(k0 + kr) * N + n0 + nn);
            uint4 u;
            u.x = f2tf32(b4.x); u.y = f2tf32(b4.y); u.z = f2tf32(b4.z); u.w = f2tf32(b4.w);
            *reinterpret_cast<uint4*>(&Bs[kr][nn]) = u;
        }
        __syncthreads();
#pragma unroll
        for (int ks = 0; ks < 2; ++ks) {
            const int kb = ks * 8;
            uint32_t af[2][4], bf[4][2];
#pragma unroll
            for (int mt = 0; mt < 2; ++mt) {
                int rb = wm * 32 + mt * 16;
                af[mt][0] = As[rb + g    ][kb + t4    ];
                af[mt][1] = As[rb + g + 8][kb + t4    ];
                af[mt][2] = As[rb + g    ][kb + t4 + 4];
                af[mt][3] = As[rb + g + 8][kb + t4 + 4];
            }
#pragma unroll
            for (int nt = 0; nt < 4; ++nt) {
                int cb = wn * 32 + nt * 8;
                bf[nt][0] = Bs[kb + t4    ][cb + g];
                bf[nt][1] = Bs[kb + t4 + 4][cb + g];
            }
#pragma unroll
            for (int mt = 0; mt < 2; ++mt)
#pragma unroll
                for (int nt = 0; nt < 4; ++nt)
                    mma_tf32(acc[mt][nt], af[mt], bf[nt]);
        }
        __syncthreads();
    }

#pragma unroll
    for (int mt = 0; mt < 2; ++mt)
#pragma unroll
        for (int nt = 0; nt < 4; ++nt) {
            int r = m0 + wm * 32 + mt * 16 + g;
            int c = n0 + wn * 32 + nt * 8 + t4 * 2;
            if (c < N) {
                float b0 = bias[c], b1 = bias[c + 1];
                if (r < M) {
                    C[(size_t)r * N + c]     = acc[mt][nt][0] + b0;
                    C[(size_t)r * N + c + 1] = acc[mt][nt][1] + b1;
                }
                if (r + 8 < M) {
                    C[(size_t)(r + 8) * N + c]     = acc[mt][nt][2] + b0;
                    C[(size_t)(r + 8) * N + c + 1] = acc[mt][nt][3] + b1;
                }
            }
        }
}

// ---------------------------------------------------------------------------
// Fused offset+attn logits: 3xBF16 split GEMM over N=288.
// blockIdx.y in [0,5): n0<192 -> W_off with tanh(x+b)*0.5 -> g_OFF;
//                      n0>=192 -> W_att, x+b raw -> g_ATT.
// ---------------------------------------------------------------------------
__global__ void gemm_off_att_3xbf16(const float* __restrict__ A,
                                    const float* __restrict__ Woff, const float* __restrict__ boff,
                                    const float* __restrict__ Watt, const float* __restrict__ batt) {
    __shared__ __align__(16) uint32_t AsH[128][12];
    __shared__ __align__(16) uint32_t AsL[128][12];
    __shared__ __align__(16) uint32_t BsH[8][72];
    __shared__ __align__(16) uint32_t BsL[8][72];
    const int tid  = threadIdx.x;
    const int lane = tid & 31;
    const int warp = tid >> 5;
    const int g  = lane >> 2, t4 = lane & 3;
    const int wm = warp >> 1, wn = warp & 1;
    const int m0 = blockIdx.x * 128, n0 = blockIdx.y * 64;
    const int M = MQ_, K = D_;
    const bool is_off = (n0 < 192);
    const float* W  = is_off ? Woff : Watt;
    const float* bb = is_off ? boff : batt;
    const int Nw    = is_off ? 192 : 96;
    const int nbase = is_off ? n0 : n0 - 192;

    float acc[2][4][4] = {};

    for (int k0 = 0; k0 < K; k0 += 16) {
        // stage A: float -> bf16 hi/lo split, packed pairs along k
#pragma unroll
        for (int p = 0; p < 2; ++p) {
            int m   = p * 64 + (tid >> 2);
            int kk4 = (tid & 3) * 4;
            float4 a4 = make_float4(0.f, 0.f, 0.f, 0.f);
            int gm = m0 + m;
            if (gm < M) a4 = *reinterpret_cast<const float4*>(A + (size_t)gm * K + k0 + kk4);
            __nv_bfloat16 h0 = __float2bfloat16_rn(a4.x);
            __nv_bfloat16 h1 = __float2bfloat16_rn(a4.y);
            __nv_bfloat16 h2 = __float2bfloat16_rn(a4.z);
            __nv_bfloat16 h3 = __float2bfloat16_rn(a4.w);
            __nv_bfloat16 l0 = __float2bfloat16_rn(a4.x - __bfloat162float(h0));
            __nv_bfloat16 l1 = __float2bfloat16_rn(a4.y - __bfloat162float(h1));
            __nv_bfloat16 l2 = __float2bfloat16_rn(a4.z - __bfloat162float(h2));
            __nv_bfloat16 l3 = __float2bfloat16_rn(a4.w - __bfloat162float(h3));
            int kp = (tid & 3) * 2;
            AsH[m][kp]     = pack_bf16(h0, h1);
            AsH[m][kp + 1] = pack_bf16(h2, h3);
            AsL[m][kp]     = pack_bf16(l0, l1);
            AsL[m][kp + 1] = pack_bf16(l2, l3);
        }
        // stage B: split W on the fly
        {
            int n  = tid & 63;
            int k2 = tid >> 6;
            int c  = nbase + n;
            bool ok = (c < Nw);
#pragma unroll
            for (int q = 0; q < 2; ++q) {
                int kk = k2 + q * 4;
                float v0 = ok ? W[(size_t)(k0 + 2 * kk)     * Nw + c] : 0.f;
                float v1 = ok ? W[(size_t)(k0 + 2 * kk + 1) * Nw + c] : 0.f;
                __nv_bfloat16 h0 = __float2bfloat16_rn(v0);
                __nv_bfloat16 h1 = __float2bfloat16_rn(v1);
                __nv_bfloat16 l0 = __float2bfloat16_rn(v0 - __bfloat162float(h0));
                __nv_bfloat16 l1 = __float2bfloat16_rn(v1 - __bfloat162float(h1));
                BsH[kk][n] = pack_bf16(h0, h1);
                BsL[kk][n] = pack_bf16(l0, l1);
            }
        }
        __syncthreads();

        uint32_t afH[2][4], afL[2][4], bfH[4][2], bfL[4][2];
#pragma unroll
        for (int mt = 0; mt < 2; ++mt) {
            int rb = wm * 32 + mt * 16;
            afH[mt][0] = AsH[rb + g    ][t4    ];
            afH[mt][1] = AsH[rb + g + 8][t4    ];
            afH[mt][2] = AsH[rb + g    ][t4 + 4];
            afH[mt][3] = AsH[rb + g + 8][t4 + 4];
            afL[mt][0] = AsL[rb + g    ][t4    ];
            afL[mt][1] = AsL[rb + g + 8][t4    ];
            afL[mt][2] = AsL[rb + g    ][t4 + 4];
            afL[mt][3] = AsL[rb + g + 8][t4 + 4];
        }
#pragma unroll
        for (int nt = 0; nt < 4; ++nt) {
            int cb = wn * 32 + nt * 8;
            bfH[nt][0] = BsH[t4    ][cb + g];
            bfH[nt][1] = BsH[t4 + 4][cb + g];
            bfL[nt][0] = BsL[t4    ][cb + g];
            bfL[nt][1] = BsL[t4 + 4][cb + g];
        }
#pragma unroll
        for (int mt = 0; mt < 2; ++mt)
#pragma unroll
            for (int nt = 0; nt < 4; ++nt)
                mma_bf16(acc[mt][nt], afH[mt], bfL[nt]);
#pragma unroll
        for (int mt = 0; mt < 2; ++mt)
#pragma unroll
            for (int nt = 0; nt < 4; ++nt)
                mma_bf16(acc[mt][nt], afL[mt], bfH[nt]);
#pragma unroll
        for (int mt = 0; mt < 2; ++mt)
#pragma unroll
            for (int nt = 0; nt < 4; ++nt)
                mma_bf16(acc[mt][nt], afH[mt], bfH[nt]);
        __syncthreads();
    }

#pragma unroll
    for (int mt = 0; mt < 2; ++mt)
#pragma unroll
        for (int nt = 0; nt < 4; ++nt) {
            int r = m0 + wm * 32 + mt * 16 + g;
            int c = nbase + wn * 32 + nt * 8 + t4 * 2;
            if (c >= Nw) continue;
            float b0 = bb[c], b1 = bb[c + 1];
            if (is_off) {
                if (r < M) {
                    g_OFF[(size_t)r * 192 + c]     = tanhf(acc[mt][nt][0] + b0) * 0.5f;
                    g_OFF[(size_t)r * 192 + c + 1] = tanhf(acc[mt][nt][1] + b1) * 0.5f;
                }
                if (r + 8 < M) {
                    g_OFF[(size_t)(r + 8) * 192 + c]     = tanhf(acc[mt][nt][2] + b0) * 0.5f;
                    g_OFF[(size_t)(r + 8) * 192 + c + 1] = tanhf(acc[mt][nt][3] + b1) * 0.5f;
                }
            } else {
                if (r < M) {
                    g_ATT[(size_t)r * 96 + c]     = acc[mt][nt][0] + b0;
                    g_ATT[(size_t)r * 96 + c + 1] = acc[mt][nt][1] + b1;
                }
                if (r + 8 < M) {
                    g_ATT[(size_t)(r + 8) * 96 + c]     = acc[mt][nt][2] + b0;
                    g_ATT[(size_t)(r + 8) * 96 + c + 1] = acc[mt][nt][3] + b1;
                }
            }
        }
}

// ---------------------------------------------------------------------------
// Merged tf32 GEMM (TN) value projection: all 3 levels in ONE launch.
// ---------------------------------------------------------------------------
__global__ void gemm_tn_tf32_all(const float* __restrict__ f0, const float* __restrict__ f1,
                                 const float* __restrict__ f2, const float* __restrict__ W,
                                 const float* __restrict__ bias) {
    __shared__ __align__(16) uint32_t As[16][136];
    __shared__ __align__(16) uint32_t Bs[16][72];
    const int tid  = threadIdx.x;
    const int lane = tid & 31;
    const int warp = tid >> 5;
    const int g  = lane >> 2, t4 = lane & 3;
    const int wm = warp >> 1, wn = warp & 1;
    const int bx = blockIdx.x;
    const int n0 = blockIdx.y * 64;
    const int b  = blockIdx.z;
    const int K = D_, N = D_;

    const float* feat; int M, sbase, mblk;
    if (bx < 50)      { feat = f0; M = 6400; sbase = 0;    mblk = bx; }
    else if (bx < 63) { feat = f1; M = 1600; sbase = 6400; mblk = bx - 50; }
    else              { feat = f2; M = 400;  sbase = 8000; mblk = bx - 63; }
    const int m0 = mblk * 128;

    const float* A = feat + (size_t)b * K * M;

    float acc[2][4][4] = {};

    for (int k0 = 0; k0 < K; k0 += 16) {
#pragma unroll
        for (int p = 0; p < 2; ++p) {
            int m = p * 64 + (tid & 15) * 4;
            int k = tid >> 4;
            float4 a4 = make_float4(0.f, 0.f, 0.f, 0.f);
            if (m0 + m < M)
                a4 = *reinterpret_cast<const float4*>(A + (size_t)(k0 + k) * M + m0 + m);
            uint4 u;
            u.x = f2tf32(a4.x); u.y = f2tf32(a4.y); u.z = f2tf32(a4.z); u.w = f2tf32(a4.w);
            *reinterpret_cast<uint4*>(&As[k][m]) = u;
        }
        {
            int kr = tid >> 4, nn = (tid & 15) * 4;
            float4 b4 = *reinterpret_cast<const float4*>(W + (size_t)(k0 + kr) * N + n0 + nn);
            uint4 u;
            u.x = f2tf32(b4.x); u.y = f2tf32(b4.y); u.z = f2tf32(b4.z); u.w = f2tf32(b4.w);
            *reinterpret_cast<uint4*>(&Bs[kr][nn]) = u;
        }
        __syncthreads();
#pragma unroll
        for (int ks = 0; ks < 2; ++ks) {
            const int kb = ks * 8;
            uint32_t af[2][4], bf[4][2];
#pragma unroll
            for (int mt = 0; mt < 2; ++mt) {
                int rb = wm * 32 + mt * 16;
                af[mt][0] = As[kb + t4    ][rb + g    ];
                af[mt][1] = As[kb + t4    ][rb + g + 8];
                af[mt][2] = As[kb + t4 + 4][rb + g    ];
                af[mt][3] = As[kb + t4 + 4][rb + g + 8];
            }
#pragma unroll
            for (int nt = 0; nt < 4; ++nt) {
                int cb = wn * 32 + nt * 8;
                bf[nt][0] = Bs[kb + t4    ][cb + g];
                bf[nt][1] = Bs[kb + t4 + 4][cb + g];
            }
#pragma unroll
            for (int mt = 0; mt < 2; ++mt)
#pragma unroll
                for (int nt = 0; nt < 4; ++nt)
                    mma_tf32(acc[mt][nt], af[mt], bf[nt]);
        }
        __syncthreads();
    }

#pragma unroll
    for (int mt = 0; mt < 2; ++mt)
#pragma unroll
        for (int nt = 0; nt < 4; ++nt) {
            int r = m0 + wm * 32 + mt * 16 + g;
            int c = n0 + wn * 32 + nt * 8 + t4 * 2;
            float b0 = bias[c], b1 = bias[c + 1];
            if (r < M) {
                size_t row = ((size_t)b * S_ + sbase + r) * D_;
                __half2 hv = __floats2half2_rn(acc[mt][nt][0] + b0, acc[mt][nt][1] + b1);
                *reinterpret_cast<__half2*>(&g_Vh[row + c]) = hv;
            }
            if (r + 8 < M) {
                size_t row = ((size_t)b * S_ + sbase + r + 8) * D_;
                __half2 hv = __floats2half2_rn(acc[mt][nt][2] + b0, acc[mt][nt][3] + b1);
                *reinterpret_cast<__half2*>(&g_Vh[row + c]) = hv;
            }
        }
}

// ---------------------------------------------------------------------------
// Sampling with inline softmax: warp per (bq, pass), 8 lanes per head,
// predicated corner loads, dual accumulators.
// ---------------------------------------------------------------------------
__global__ void sample_kernel(const float* __restrict__ ref) {
    const int gw   = (blockIdx.x * blockDim.x + threadIdx.x) >> 5;
    const int lane = threadIdx.x & 31;
    if (gw >= MQ_ * 2) return;

    const int bq   = gw >> 1;
    const int pass = gw & 1;
    const int b    = bq / Q_;
    const int grp  = lane >> 3;
    const int cl   = (lane & 7) * 4;

    const float rx = __ldg(ref + (size_t)bq * 2 + 0);
    const float ry = __ldg(ref + (size_t)bq * 2 + 1);

    const int Wls[3] = {80, 40, 20};
    const int bas[3] = {0, 6400, 8000};

    const int h = grp + pass * 4;
    const float* offp = g_OFF + (size_t)bq * 192 + h * 24;
    const float* attp = g_ATT + (size_t)bq * 96 + h * 12;
    const __half* Vb  = g_Vh + (size_t)b * S_ * D_ + h * HD_ + cl;

    // inline softmax over this head's 12 (level,point) logits
    float wgt[12];
    float mx = -1e30f;
#pragma unroll
    for (int j = 0; j < 12; ++j) { wgt[j] = __ldg(attp + j); mx = fmaxf(mx, wgt[j]); }
    float ssum = 0.f;
#pragma unroll
    for (int j = 0; j < 12; ++j) { wgt[j] = __expf(wgt[j] - mx); ssum += wgt[j]; }
    const float sinv = 1.f / ssum;

    float4 acc0 = make_float4(0.f, 0.f, 0.f, 0.f);
    float4 acc1 = make_float4(0.f, 0.f, 0.f, 0.f);

#pragma unroll
    for (int l = 0; l < NL_; ++l) {
        const int Wl = Wls[l], base = bas[l];
        const float Wlf = (float)Wl;
#pragma unroll
        for (int p = 0; p < NP_; ++p) {
            float4& acc = (p & 1) ? acc1 : acc0;
            const float ox = __ldg(offp + (l * 4 + p) * 2 + 0);
            const float oy = __ldg(offp + (l * 4 + p) * 2 + 1);
            const float w  = wgt[l * 4 + p] * sinv;
            const float ix = (rx + ox) * Wlf - 0.5f;
            const float iy = (ry + oy) * Wlf - 0.5f;
            const float x0f = floorf(ix), y0f = floorf(iy);
            const int x0 = (int)x0f, y0 = (int)y0f;
            const float fx = ix - x0f, fy = iy - y0f;
            const float w00 = w * (1.f - fx) * (1.f - fy);
            const float w01 = w * fx * (1.f - fy);
            const float w10 = w * (1.f - fx) * fy;
            const float w11 = w * fx * fy;

            const bool xin0 = (x0 >= 0) && (x0 < Wl);
            const bool xin1 = (x0 + 1 >= 0) && (x0 + 1 < Wl);
            const bool yin0 = (y0 >= 0) && (y0 < Wl);
            const bool yin1 = (y0 + 1 >= 0) && (y0 + 1 < Wl);

#define ACC_CORNER(cond, idx, wgt_)                                             \
            if (cond) {                                                         \
                uint2 u = *reinterpret_cast<const uint2*>(Vb + (size_t)(idx) * D_); \
                float2 f0 = __half22float2(*reinterpret_cast<__half2*>(&u.x));  \
                float2 f1 = __half22float2(*reinterpret_cast<__half2*>(&u.y));  \
                acc.x = fmaf(wgt_, f0.x, acc.x); acc.y = fmaf(wgt_, f0.y, acc.y); \
                acc.z = fmaf(wgt_, f1.x, acc.z); acc.w = fmaf(wgt_, f1.y, acc.w); \
            }

            ACC_CORNER(xin0 && yin0, base + y0 * Wl + x0,           w00)
            ACC_CORNER(xin1 && yin0, base + y0 * Wl + x0 + 1,       w01)
            ACC_CORNER(xin0 && yin1, base + (y0 + 1) * Wl + x0,     w10)
            ACC_CORNER(xin1 && yin1, base + (y0 + 1) * Wl + x0 + 1, w11)
#undef ACC_CORNER
        }
    }

    float4 acc;
    acc.x = acc0.x + acc1.x; acc.y = acc0.y + acc1.y;
    acc.z = acc0.z + acc1.z; acc.w = acc0.w + acc1.w;
    *reinterpret_cast<float4*>(g_MID + (size_t)bq * D_ + h * HD_ + cl) = acc;
}

// ---------------------------------------------------------------------------
// Launch: valproj on side stream, overlapped with fused offset+attn GEMM.
// ---------------------------------------------------------------------------
extern "C" void kernel_launch(void* const* d_in, const int* in_sizes, int n_in,
                              void* d_out, int out_size) {
    const float* query = (const float*)d_in[0];
    const float* feat0 = (const float*)d_in[1];
    const float* feat1 = (const float*)d_in[2];
    const float* feat2 = (const float*)d_in[3];
    const float* refp  = (const float*)d_in[4];
    const float* W_off = (const float*)d_in[5];
    const float* b_off = (const float*)d_in[6];
    const float* W_att = (const float*)d_in[7];
    const float* b_att = (const float*)d_in[8];
    const float* W_val = (const float*)d_in[9];
    const float* b_val = (const float*)d_in[10];
    const float* W_out = (const float*)d_in[11];
    const float* b_out = (const float*)d_in[12];
    float* out = (float*)d_out;

    float* pMID; cudaGetSymbolAddress((void**)&pMID, g_MID);

    static cudaStream_t s1 = nullptr;
    static cudaEvent_t evRoot = nullptr, evV = nullptr;
    if (s1 == nullptr) {
        cudaStreamCreateWithFlags(&s1, cudaStreamNonBlocking);
        cudaEventCreateWithFlags(&evRoot, cudaEventDisableTiming);
        cudaEventCreateWithFlags(&evV,    cudaEventDisableTiming);
    }

    dim3 blk(256);

    // fork
    cudaEventRecord(evRoot, 0);
    cudaStreamWaitEvent(s1, evRoot, 0);

    // side stream: merged value projection
    gemm_tn_tf32_all<<<dim3(67, 4, B_), blk, 0, s1>>>(feat0, feat1, feat2, W_val, b_val);
    cudaEventRecord(evV, s1);

    // main stream (concurrent): fused offset+attn logits (N=288)
    gemm_off_att_3xbf16<<<dim3((MQ_ + 127) / 128, 5), blk>>>(query, W_off, b_off, W_att, b_att);

    // join: sampler needs V + OFF + ATT
    cudaStreamWaitEvent(0, evV, 0);

    // bilinear sampling (inline softmax) -> MID
    sample_kernel<<<(MQ_ * 2 + 7) / 8, 256>>>(refp);

    // output projection (tf32)
    gemm_nn_tf32<<<dim3((MQ_ + 127) / 128, 4), blk>>>(pMID, W_out, b_out, out, MQ_, D_, D_);
}

// round 12
// speedup vs baseline: 1.2691x; 1.0048x over previous
#include <cuda_runtime.h>
#include <cuda_fp16.h>
#include <cuda_bf16.h>
#include <cstdint>

// ---------------------------------------------------------------------------
// MultiScaleDETR deformable attention.
// B=4, Q=8400, D=256, nH=8, hd=32, L=3 (80x80,40x40,20x20), P=4.
// tf32 GEMMs (double-buffered) for value/output; fused 3xBF16 split GEMM
// (double-buffered, N=288) for offset+attn logits; softmax fused into the
// fp16-gather sampler; valproj overlapped on a side stream.
// ---------------------------------------------------------------------------

#define B_    4
#define Q_    8400
#define D_    256
#define NH_   8
#define HD_   32
#define NL_   3
#define NP_   4
#define S_    8400
#define MQ_   (B_ * Q_)      // 33600

__device__ __half g_Vh [B_ * S_ * D_];  // value projection, fp16
__device__ float  g_OFF[MQ_ * 192];     // tanh(offset_logit)*0.5
__device__ float  g_ATT[MQ_ * 96];      // raw attn logits (softmax in sampler)
__device__ float  g_MID[MQ_ * D_];      // attention output pre-W_out

// ---------------------------------------------------------------------------
// mma helpers
// ---------------------------------------------------------------------------
__device__ __forceinline__ uint32_t f2tf32(float f) {
    uint32_t u;
    asm("cvt.rna.tf32.f32 %0, %1;" : "=r"(u) : "f"(f));
    return u;
}

__device__ __forceinline__ void mma_tf32(float* d, const uint32_t* a, const uint32_t* b) {
    asm volatile(
        "mma.sync.aligned.m16n8k8.row.col.f32.tf32.tf32.f32 "
        "{%0,%1,%2,%3}, {%4,%5,%6,%7}, {%8,%9}, {%0,%1,%2,%3};\n"
        : "+f"(d[0]), "+f"(d[1]), "+f"(d[2]), "+f"(d[3])
        : "r"(a[0]), "r"(a[1]), "r"(a[2]), "r"(a[3]), "r"(b[0]), "r"(b[1]));
}

__device__ __forceinline__ void mma_bf16(float* d, const uint32_t* a, const uint32_t* b) {
    asm volatile(
        "mma.sync.aligned.m16n8k16.row.col.f32.bf16.bf16.f32 "
        "{%0,%1,%2,%3}, {%4,%5,%6,%7}, {%8,%9}, {%0,%1,%2,%3};\n"
        : "+f"(d[0]), "+f"(d[1]), "+f"(d[2]), "+f"(d[3])
        : "r"(a[0]), "r"(a[1]), "r"(a[2]), "r"(a[3]), "r"(b[0]), "r"(b[1]));
}

__device__ __forceinline__ uint32_t pack_bf16(__nv_bfloat16 a, __nv_bfloat16 b) {
    __nv_bfloat162 h; h.x = a; h.y = b;
    return *reinterpret_cast<uint32_t*>(&h);
}

// ---------------------------------------------------------------------------
// tf32 GEMM (NN), double-buffered: C = A @ B + bias (output projection)
// ---------------------------------------------------------------------------
__global__ void gemm_nn_tf32(const float* __restrict__ A, const float* __restrict__ Bm,
                             const float* __restrict__ bias, float* __restrict__ C,
                             int M, int N, int K) {
    __shared__ __align__(16) uint32_t As[2][128][20];
    __shared__ __align__(16) uint32_t Bs[2][16][72];
    const int tid  = threadIdx.x;
    const int lane = tid & 31;
    const int warp = tid >> 5;
    const int g  = lane >> 2, t4 = lane & 3;
    const int wm = warp >> 1, wn = warp & 1;
    const int m0 = blockIdx.x * 128, n0 = blockIdx.y * 64;

    const int am  = tid >> 2;           // A row within tile half
    const int ak  = (tid & 3) * 4;      // A k offset
    const int bkr = tid >> 4;           // B k row
    const int bnn = (tid & 15) * 4;     // B n offset

    float acc[2][4][4] = {};
    float4 pa[2], pb;

    // prologue: load tile 0 into regs, store to buf 0
#pragma unroll
    for (int p = 0; p < 2; ++p) {
        int gm = m0 + p * 64 + am;
        pa[p] = make_float4(0.f, 0.f, 0.f, 0.f);
        if (gm < M) pa[p] = *reinterpret_cast<const float4*>(A + (size_t)gm * K + ak);
    }
    pb = make_float4(0.f, 0.f, 0.f, 0.f);
    if (n0 + bnn < N) pb = *reinterpret_cast<const float4*>(Bm + (size_t)bkr * N + n0 + bnn);
#pragma unroll
    for (int p = 0; p < 2; ++p) {
        uint4 u;
        u.x = f2tf32(pa[p].x); u.y = f2tf32(pa[p].y); u.z = f2tf32(pa[p].z); u.w = f2tf32(pa[p].w);
        *reinterpret_cast<uint4*>(&As[0][p * 64 + am][ak]) = u;
    }
    {
        uint4 u;
        u.x = f2tf32(pb.x); u.y = f2tf32(pb.y); u.z = f2tf32(pb.z); u.w = f2tf32(pb.w);
        *reinterpret_cast<uint4*>(&Bs[0][bkr][bnn]) = u;
    }
    __syncthreads();

    int cur = 0;
    for (int k0 = 0; k0 < K; k0 += 16) {
        const bool has_next = (k0 + 16 < K);
        const int nxt = cur ^ 1;

        // prefetch next tile into registers
        if (has_next) {
#pragma unroll
            for (int p = 0; p < 2; ++p) {
                int gm = m0 + p * 64 + am;
                pa[p] = make_float4(0.f, 0.f, 0.f, 0.f);
                if (gm < M) pa[p] = *reinterpret_cast<const float4*>(A + (size_t)gm * K + k0 + 16 + ak);
            }
            pb = make_float4(0.f, 0.f, 0.f, 0.f);
            if (n0 + bnn < N) pb = *reinterpret_cast<const float4*>(Bm + (size_t)(k0 + 16 + bkr) * N + n0 + bnn);
        }

        // compute current tile
#pragma unroll
        for (int ks = 0; ks < 2; ++ks) {
            const int kb = ks * 8;
            uint32_t af[2][4], bf[4][2];
#pragma unroll
            for (int mt = 0; mt < 2; ++mt) {
                int rb = wm * 32 + mt * 16;
                af[mt][0] = As[cur][rb + g    ][kb + t4    ];
                af[mt][1] = As[cur][rb + g + 8][kb + t4    ];
                af[mt][2] = As[cur][rb + g    ][kb + t4 + 4];
                af[mt][3] = As[cur][rb + g + 8][kb + t4 + 4];
            }
#pragma unroll
            for (int nt = 0; nt < 4; ++nt) {
                int cb = wn * 32 + nt * 8;
                bf[nt][0] = Bs[cur][kb + t4    ][cb + g];
                bf[nt][1] = Bs[cur][kb + t4 + 4][cb + g];
            }
#pragma unroll
            for (int mt = 0; mt < 2; ++mt)
#pragma unroll
                for (int nt = 0; nt < 4; ++nt)
                    mma_tf32(acc[mt][nt], af[mt], bf[nt]);
        }

        // store prefetched tile to other buffer
        if (has_next) {
#pragma unroll
            for (int p = 0; p < 2; ++p) {
                uint4 u;
                u.x = f2tf32(pa[p].x); u.y = f2tf32(pa[p].y); u.z = f2tf32(pa[p].z); u.w = f2tf32(pa[p].w);
                *reinterpret_cast<uint4*>(&As[nxt][p * 64 + am][ak]) = u;
            }
            uint4 u;
            u.x = f2tf32(pb.x); u.y = f2tf32(pb.y); u.z = f2tf32(pb.z); u.w = f2tf32(pb.w);
            *reinterpret_cast<uint4*>(&Bs[nxt][bkr][bnn]) = u;
        }
        __syncthreads();
        cur = nxt;
    }

#pragma unroll
    for (int mt = 0; mt < 2; ++mt)
#pragma unroll
        for (int nt = 0; nt < 4; ++nt) {
            int r = m0 + wm * 32 + mt * 16 + g;
            int c = n0 + wn * 32 + nt * 8 + t4 * 2;
            if (c < N) {
                float b0 = bias[c], b1 = bias[c + 1];
                if (r < M) {
                    C[(size_t)r * N + c]     = acc[mt][nt][0] + b0;
                    C[(size_t)r * N + c + 1] = acc[mt][nt][1] + b1;
                }
                if (r + 8 < M) {
                    C[(size_t)(r + 8) * N + c]     = acc[mt][nt][2] + b0;
                    C[(size_t)(r + 8) * N + c + 1] = acc[mt][nt][3] + b1;
                }
            }
        }
}

// ---------------------------------------------------------------------------
// Fused offset+attn logits: 3xBF16 split GEMM over N=288, double-buffered.
// n0<192 -> W_off with tanh(x+b)*0.5 -> g_OFF;  n0>=192 -> W_att raw -> g_ATT.
// ---------------------------------------------------------------------------
__global__ void gemm_off_att_3xbf16(const float* __restrict__ A,
                                    const float* __restrict__ Woff, const float* __restrict__ boff,
                                    const float* __restrict__ Watt, const float* __restrict__ batt) {
    __shared__ __align__(16) uint32_t AsH[2][128][12];
    __shared__ __align__(16) uint32_t AsL[2][128][12];
    __shared__ __align__(16) uint32_t BsH[2][8][72];
    __shared__ __align__(16) uint32_t BsL[2][8][72];
    const int tid  = threadIdx.x;
    const int lane = tid & 31;
    const int warp = tid >> 5;
    const int g  = lane >> 2, t4 = lane & 3;
    const int wm = warp >> 1, wn = warp & 1;
    const int m0 = blockIdx.x * 128, n0 = blockIdx.y * 64;
    const int M = MQ_, K = D_;
    const bool is_off = (n0 < 192);
    const float* W  = is_off ? Woff : Watt;
    const float* bb = is_off ? boff : batt;
    const int Nw    = is_off ? 192 : 96;
    const int nbase = is_off ? n0 : n0 - 192;

    const int am  = tid >> 2;
    const int ak4 = (tid & 3) * 4;
    const int akp = (tid & 3) * 2;
    const int bn  = tid & 63;
    const int bk2 = tid >> 6;
    const int bc  = nbase + bn;
    const bool bok = (bc < Nw);

    float acc[2][4][4] = {};
    float4 pa[2];
    float pbv[4];

    // ---- prologue: tile 0 ----
#pragma unroll
    for (int p = 0; p < 2; ++p) {
        int gm = m0 + p * 64 + am;
        pa[p] = make_float4(0.f, 0.f, 0.f, 0.f);
        if (gm < M) pa[p] = *reinterpret_cast<const float4*>(A + (size_t)gm * K + ak4);
    }
#pragma unroll
    for (int q = 0; q < 2; ++q) {
        int kk = bk2 + q * 4;
        pbv[q * 2]     = bok ? W[(size_t)(2 * kk)     * Nw + bc] : 0.f;
        pbv[q * 2 + 1] = bok ? W[(size_t)(2 * kk + 1) * Nw + bc] : 0.f;
    }
#pragma unroll
    for (int p = 0; p < 2; ++p) {
        __nv_bfloat16 h0 = __float2bfloat16_rn(pa[p].x);
        __nv_bfloat16 h1 = __float2bfloat16_rn(pa[p].y);
        __nv_bfloat16 h2 = __float2bfloat16_rn(pa[p].z);
        __nv_bfloat16 h3 = __float2bfloat16_rn(pa[p].w);
        __nv_bfloat16 l0 = __float2bfloat16_rn(pa[p].x - __bfloat162float(h0));
        __nv_bfloat16 l1 = __float2bfloat16_rn(pa[p].y - __bfloat162float(h1));
        __nv_bfloat16 l2 = __float2bfloat16_rn(pa[p].z - __bfloat162float(h2));
        __nv_bfloat16 l3 = __float2bfloat16_rn(pa[p].w - __bfloat162float(h3));
        int m = p * 64 + am;
        AsH[0][m][akp]     = pack_bf16(h0, h1);
        AsH[0][m][akp + 1] = pack_bf16(h2, h3);
        AsL[0][m][akp]     = pack_bf16(l0, l1);
        AsL[0][m][akp + 1] = pack_bf16(l2, l3);
    }
#pragma unroll
    for (int q = 0; q < 2; ++q) {
        int kk = bk2 + q * 4;
        __nv_bfloat16 h0 = __float2bfloat16_rn(pbv[q * 2]);
        __nv_bfloat16 h1 = __float2bfloat16_rn(pbv[q * 2 + 1]);
        __nv_bfloat16 l0 = __float2bfloat16_rn(pbv[q * 2]     - __bfloat162float(h0));
        __nv_bfloat16 l1 = __float2bfloat16_rn(pbv[q * 2 + 1] - __bfloat162float(h1));
        BsH[0][kk][bn] = pack_bf16(h0, h1);
        BsL[0][kk][bn] = pack_bf16(l0, l1);
    }
    __syncthreads();

    int cur = 0;
    for (int k0 = 0; k0 < K; k0 += 16) {
        const bool has_next = (k0 + 16 < K);
        const int nxt = cur ^ 1;

        // prefetch next tile
        if (has_next) {
#pragma unroll
            for (int p = 0; p < 2; ++p) {
                int gm = m0 + p * 64 + am;
                pa[p] = make_float4(0.f, 0.f, 0.f, 0.f);
                if (gm < M) pa[p] = *reinterpret_cast<const float4*>(A + (size_t)gm * K + k0 + 16 + ak4);
            }
#pragma unroll
            for (int q = 0; q < 2; ++q) {
                int kk = bk2 + q * 4;
                pbv[q * 2]     = bok ? W[(size_t)(k0 + 16 + 2 * kk)     * Nw + bc] : 0.f;
                pbv[q * 2 + 1] = bok ? W[(size_t)(k0 + 16 + 2 * kk + 1) * Nw + bc] : 0.f;
            }
        }

        // compute current tile
        {
            uint32_t afH[2][4], afL[2][4], bfH[4][2], bfL[4][2];
#pragma unroll
            for (int mt = 0; mt < 2; ++mt) {
                int rb = wm * 32 + mt * 16;
                afH[mt][0] = AsH[cur][rb + g    ][t4    ];
                afH[mt][1] = AsH[cur][rb + g + 8][t4    ];
                afH[mt][2] = AsH[cur][rb + g    ][t4 + 4];
                afH[mt][3] = AsH[cur][rb + g + 8][t4 + 4];
                afL[mt][0] = AsL[cur][rb + g    ][t4    ];
                afL[mt][1] = AsL[cur][rb + g + 8][t4    ];
                afL[mt][2] = AsL[cur][rb + g    ][t4 + 4];
                afL[mt][3] = AsL[cur][rb + g + 8][t4 + 4];
            }
#pragma unroll
            for (int nt = 0; nt < 4; ++nt) {
                int cb = wn * 32 + nt * 8;
                bfH[nt][0] = BsH[cur][t4    ][cb + g];
                bfH[nt][1] = BsH[cur][t4 + 4][cb + g];
                bfL[nt][0] = BsL[cur][t4    ][cb + g];
                bfL[nt][1] = BsL[cur][t4 + 4][cb + g];
            }
#pragma unroll
            for (int mt = 0; mt < 2; ++mt)
#pragma unroll
                for (int nt = 0; nt < 4; ++nt)
                    mma_bf16(acc[mt][nt], afH[mt], bfL[nt]);
#pragma unroll
            for (int mt = 0; mt < 2; ++mt)
#pragma unroll
                for (int nt = 0; nt < 4; ++nt)
                    mma_bf16(acc[mt][nt], afL[mt], bfH[nt]);
#pragma unroll
            for (int mt = 0; mt < 2; ++mt)
#pragma unroll
                for (int nt = 0; nt < 4; ++nt)
                    mma_bf16(acc[mt][nt], afH[mt], bfH[nt]);
        }

        // store prefetched tile (split to hi/lo) into other buffer
        if (has_next) {
#pragma unroll
            for (int p = 0; p < 2; ++p) {
                __nv_bfloat16 h0 = __float2bfloat16_rn(pa[p].x);
                __nv_bfloat16 h1 = __float2bfloat16_rn(pa[p].y);
                __nv_bfloat16 h2 = __float2bfloat16_rn(pa[p].z);
                __nv_bfloat16 h3 = __float2bfloat16_rn(pa[p].w);
                __nv_bfloat16 l0 = __float2bfloat16_rn(pa[p].x - __bfloat162float(h0));
                __nv_bfloat16 l1 = __float2bfloat16_rn(pa[p].y - __bfloat162float(h1));
                __nv_bfloat16 l2 = __float2bfloat16_rn(pa[p].z - __bfloat162float(h2));
                __nv_bfloat16 l3 = __float2bfloat16_rn(pa[p].w - __bfloat162float(h3));
                int m = p * 64 + am;
                AsH[nxt][m][akp]     = pack_bf16(h0, h1);
                AsH[nxt][m][akp + 1] = pack_bf16(h2, h3);
                AsL[nxt][m][akp]     = pack_bf16(l0, l1);
                AsL[nxt][m][akp + 1] = pack_bf16(l2, l3);
            }
#pragma unroll
            for (int q = 0; q < 2; ++q) {
                int kk = bk2 + q * 4;
                __nv_bfloat16 h0 = __float2bfloat16_rn(pbv[q * 2]);
                __nv_bfloat16 h1 = __float2bfloat16_rn(pbv[q * 2 + 1]);
                __nv_bfloat16 l0 = __float2bfloat16_rn(pbv[q * 2]     - __bfloat162float(h0));
                __nv_bfloat16 l1 = __float2bfloat16_rn(pbv[q * 2 + 1] - __bfloat162float(h1));
                BsH[nxt][kk][bn] = pack_bf16(h0, h1);
                BsL[nxt][kk][bn] = pack_bf16(l0, l1);
            }
        }
        __syncthreads();
        cur = nxt;
    }

#pragma unroll
    for (int mt = 0; mt < 2; ++mt)
#pragma unroll
        for (int nt = 0; nt < 4; ++nt) {
            int r = m0 + wm * 32 + mt * 16 + g;
            int c = nbase + wn * 32 + nt * 8 + t4 * 2;
            if (c >= Nw) continue;
            float b0 = bb[c], b1 = bb[c + 1];
            if (is_off) {
                if (r < M) {
                    g_OFF[(size_t)r * 192 + c]     = tanhf(acc[mt][nt][0] + b0) * 0.5f;
                    g_OFF[(size_t)r * 192 + c + 1] = tanhf(acc[mt][nt][1] + b1) * 0.5f;
                }
                if (r + 8 < M) {
                    g_OFF[(size_t)(r + 8) * 192 + c]     = tanhf(acc[mt][nt][2] + b0) * 0.5f;
                    g_OFF[(size_t)(r + 8) * 192 + c + 1] = tanhf(acc[mt][nt][3] + b1) * 0.5f;
                }
            } else {
                if (r < M) {
                    g_ATT[(size_t)r * 96 + c]     = acc[mt][nt][0] + b0;
                    g_ATT[(size_t)r * 96 + c + 1] = acc[mt][nt][1] + b1;
                }
                if (r + 8 < M) {
                    g_ATT[(size_t)(r + 8) * 96 + c]     = acc[mt][nt][2] + b0;
                    g_ATT[(size_t)(r + 8) * 96 + c + 1] = acc[mt][nt][3] + b1;
                }
            }
        }
}

// ---------------------------------------------------------------------------
// Merged tf32 GEMM (TN) value projection: all 3 levels in ONE launch.
// (hidden under the off_att chain on a side stream; unchanged)
// ---------------------------------------------------------------------------
__global__ void gemm_tn_tf32_all(const float* __restrict__ f0, const float* __restrict__ f1,
                                 const float* __restrict__ f2, const float* __restrict__ W,
                                 const float* __restrict__ bias) {
    __shared__ __align__(16) uint32_t As[16][136];
    __shared__ __align__(16) uint32_t Bs[16][72];
    const int tid  = threadIdx.x;
    const int lane = tid & 31;
    const int warp = tid >> 5;
    const int g  = lane >> 2, t4 = lane & 3;
    const int wm = warp >> 1, wn = warp & 1;
    const int bx = blockIdx.x;
    const int n0 = blockIdx.y * 64;
    const int b  = blockIdx.z;
    const int K = D_, N = D_;

    const float* feat; int M, sbase, mblk;
    if (bx < 50)      { feat = f0; M = 6400; sbase = 0;    mblk = bx; }
    else if (bx < 63) { feat = f1; M = 1600; sbase = 6400; mblk = bx - 50; }
    else              { feat = f2; M = 400;  sbase = 8000; mblk = bx - 63; }
    const int m0 = mblk * 128;

    const float* A = feat + (size_t)b * K * M;

    float acc[2][4][4] = {};

    for (int k0 = 0; k0 < K; k0 += 16) {
#pragma unroll
        for (int p = 0; p < 2; ++p) {
            int m = p * 64 + (tid & 15) * 4;
            int k = tid >> 4;
            float4 a4 = make_float4(0.f, 0.f, 0.f, 0.f);
            if (m0 + m < M)
                a4 = *reinterpret_cast<const float4*>(A + (size_t)(k0 + k) * M + m0 + m);
            uint4 u;
            u.x = f2tf32(a4.x); u.y = f2tf32(a4.y); u.z = f2tf32(a4.z); u.w = f2tf32(a4.w);
            *reinterpret_cast<uint4*>(&As[k][m]) = u;
        }
        {
            int kr = tid >> 4, nn = (tid & 15) * 4;
            float4 b4 = *reinterpret_cast<const float4*>(W + (size_t)(k0 + kr) * N + n0 + nn);
            uint4 u;
            u.x = f2tf32(b4.x); u.y = f2tf32(b4.y); u.z = f2tf32(b4.z); u.w = f2tf32(b4.w);
            *reinterpret_cast<uint4*>(&Bs[kr][nn]) = u;
        }
        __syncthreads();
#pragma unroll
        for (int ks = 0; ks < 2; ++ks) {
            const int kb = ks * 8;
            uint32_t af[2][4], bf[4][2];
#pragma unroll
            for (int mt = 0; mt < 2; ++mt) {
                int rb = wm * 32 + mt * 16;
                af[mt][0] = As[kb + t4    ][rb + g    ];
                af[mt][1] = As[kb + t4    ][rb + g + 8];
                af[mt][2] = As[kb + t4 + 4][rb + g    ];
                af[mt][3] = As[kb + t4 + 4][rb + g + 8];
            }
#pragma unroll
            for (int nt = 0; nt < 4; ++nt) {
                int cb = wn * 32 + nt * 8;
                bf[nt][0] = Bs[kb + t4    ][cb + g];
                bf[nt][1] = Bs[kb + t4 + 4][cb + g];
            }
#pragma unroll
            for (int mt = 0; mt < 2; ++mt)
#pragma unroll
                for (int nt = 0; nt < 4; ++nt)
                    mma_tf32(acc[mt][nt], af[mt], bf[nt]);
        }
        __syncthreads();
    }

#pragma unroll
    for (int mt = 0; mt < 2; ++mt)
#pragma unroll
        for (int nt = 0; nt < 4; ++nt) {
            int r = m0 + wm * 32 + mt * 16 + g;
            int c = n0 + wn * 32 + nt * 8 + t4 * 2;
            float b0 = bias[c], b1 = bias[c + 1];
            if (r < M) {
                size_t row = ((size_t)b * S_ + sbase + r) * D_;
                __half2 hv = __floats2half2_rn(acc[mt][nt][0] + b0, acc[mt][nt][1] + b1);
                *reinterpret_cast<__half2*>(&g_Vh[row + c]) = hv;
            }
            if (r + 8 < M) {
                size_t row = ((size_t)b * S_ + sbase + r + 8) * D_;
                __half2 hv = __floats2half2_rn(acc[mt][nt][2] + b0, acc[mt][nt][3] + b1);
                *reinterpret_cast<__half2*>(&g_Vh[row + c]) = hv;
            }
        }
}

// ---------------------------------------------------------------------------
// Sampling with inline softmax: warp per (bq, pass), 8 lanes per head,
// predicated corner loads, dual accumulators.
// ---------------------------------------------------------------------------
__global__ void sample_kernel(const float* __restrict__ ref) {
    const int gw   = (blockIdx.x * blockDim.x + threadIdx.x) >> 5;
    const int lane = threadIdx.x & 31;
    if (gw >= MQ_ * 2) return;

    const int bq   = gw >> 1;
    const int pass = gw & 1;
    const int b    = bq / Q_;
    const int grp  = lane >> 3;
    const int cl   = (lane & 7) * 4;

    const float rx = __ldg(ref + (size_t)bq * 2 + 0);
    const float ry = __ldg(ref + (size_t)bq * 2 + 1);

    const int Wls[3] = {80, 40, 20};
    const int bas[3] = {0, 6400, 8000};

    const int h = grp + pass * 4;
    const float* offp = g_OFF + (size_t)bq * 192 + h * 24;
    const float* attp = g_ATT + (size_t)bq * 96 + h * 12;
    const __half* Vb  = g_Vh + (size_t)b * S_ * D_ + h * HD_ + cl;

    // inline softmax over this head's 12 (level,point) logits
    float wgt[12];
    float mx = -1e30f;
#pragma unroll
    for (int j = 0; j < 12; ++j) { wgt[j] = __ldg(attp + j); mx = fmaxf(mx, wgt[j]); }
    float ssum = 0.f;
#pragma unroll
    for (int j = 0; j < 12; ++j) { wgt[j] = __expf(wgt[j] - mx); ssum += wgt[j]; }
    const float sinv = 1.f / ssum;

    float4 acc0 = make_float4(0.f, 0.f, 0.f, 0.f);
    float4 acc1 = make_float4(0.f, 0.f, 0.f, 0.f);

#pragma unroll
    for (int l = 0; l < NL_; ++l) {
        const int Wl = Wls[l], base = bas[l];
        const float Wlf = (float)Wl;
#pragma unroll
        for (int p = 0; p < NP_; ++p) {
            float4& acc = (p & 1) ? acc1 : acc0;
            const float ox = __ldg(offp + (l * 4 + p) * 2 + 0);
            const float oy = __ldg(offp + (l * 4 + p) * 2 + 1);
            const float w  = wgt[l * 4 + p] * sinv;
            const float ix = (rx + ox) * Wlf - 0.5f;
            const float iy = (ry + oy) * Wlf - 0.5f;
            const float x0f = floorf(ix), y0f = floorf(iy);
            const int x0 = (int)x0f, y0 = (int)y0f;
            const float fx = ix - x0f, fy = iy - y0f;
            const float w00 = w * (1.f - fx) * (1.f - fy);
            const float w01 = w * fx * (1.f - fy);
            const float w10 = w * (1.f - fx) * fy;
            const float w11 = w * fx * fy;

            const bool xin0 = (x0 >= 0) && (x0 < Wl);
            const bool xin1 = (x0 + 1 >= 0) && (x0 + 1 < Wl);
            const bool yin0 = (y0 >= 0) && (y0 < Wl);
            const bool yin1 = (y0 + 1 >= 0) && (y0 + 1 < Wl);

#define ACC_CORNER(cond, idx, wgt_)                                             \
            if (cond) {                                                         \
                uint2 u = *reinterpret_cast<const uint2*>(Vb + (size_t)(idx) * D_); \
                float2 f0 = __half22float2(*reinterpret_cast<__half2*>(&u.x));  \
                float2 f1 = __half22float2(*reinterpret_cast<__half2*>(&u.y));  \
                acc.x = fmaf(wgt_, f0.x, acc.x); acc.y = fmaf(wgt_, f0.y, acc.y); \
                acc.z = fmaf(wgt_, f1.x, acc.z); acc.w = fmaf(wgt_, f1.y, acc.w); \
            }

            ACC_CORNER(xin0 && yin0, base + y0 * Wl + x0,           w00)
            ACC_CORNER(xin1 && yin0, base + y0 * Wl + x0 + 1,       w01)
            ACC_CORNER(xin0 && yin1, base + (y0 + 1) * Wl + x0,     w10)
            ACC_CORNER(xin1 && yin1, base + (y0 + 1) * Wl + x0 + 1, w11)
#undef ACC_CORNER
        }
    }

    float4 acc;
    acc.x = acc0.x + acc1.x; acc.y = acc0.y + acc1.y;
    acc.z = acc0.z + acc1.z; acc.w = acc0.w + acc1.w;
    *reinterpret_cast<float4*>(g_MID + (size_t)bq * D_ + h * HD_ + cl) = acc;
}

// ---------------------------------------------------------------------------
// Launch: valproj on side stream, overlapped with fused offset+attn GEMM.
// ---------------------------------------------------------------------------
extern "C" void kernel_launch(void* const* d_in, const int* in_sizes, int n_in,
                              void* d_out, int out_size) {
    const float* query = (const float*)d_in[0];
    const float* feat0 = (const float*)d_in[1];
    const float* feat1 = (const float*)d_in[2];
    const float* feat2 = (const float*)d_in[3];
    const float* refp  = (const float*)d_in[4];
    const float* W_off = (const float*)d_in[5];
    const float* b_off = (const float*)d_in[6];
    const float* W_att = (const float*)d_in[7];
    const float* b_att = (const float*)d_in[8];
    const float* W_val = (const float*)d_in[9];
    const float* b_val = (const float*)d_in[10];
    const float* W_out = (const float*)d_in[11];
    const float* b_out = (const float*)d_in[12];
    float* out = (float*)d_out;

    float* pMID; cudaGetSymbolAddress((void**)&pMID, g_MID);

    static cudaStream_t s1 = nullptr;
    static cudaEvent_t evRoot = nullptr, evV = nullptr;
    if (s1 == nullptr) {
        cudaStreamCreateWithFlags(&s1, cudaStreamNonBlocking);
        cudaEventCreateWithFlags(&evRoot, cudaEventDisableTiming);
        cudaEventCreateWithFlags(&evV,    cudaEventDisableTiming);
    }

    dim3 blk(256);

    // fork
    cudaEventRecord(evRoot, 0);
    cudaStreamWaitEvent(s1, evRoot, 0);

    // side stream: merged value projection
    gemm_tn_tf32_all<<<dim3(67, 4, B_), blk, 0, s1>>>(feat0, feat1, feat2, W_val, b_val);
    cudaEventRecord(evV, s1);

    // main stream (concurrent): fused offset+attn logits (N=288)
    gemm_off_att_3xbf16<<<dim3((MQ_ + 127) / 128, 5), blk>>>(query, W_off, b_off, W_att, b_att);

    // join: sampler needs V + OFF + ATT
    cudaStreamWaitEvent(0, evV, 0);

    // bilinear sampling (inline softmax) -> MID
    sample_kernel<<<(MQ_ * 2 + 7) / 8, 256>>>(refp);

    // output projection (tf32, double-buffered)
    gemm_nn_tf32<<<dim3((MQ_ + 127) / 128, 4), blk>>>(pMID, W_out, b_out, out, MQ_, D_, D_);
}